// round 4
// baseline (speedup 1.0000x reference)
#include <cuda_runtime.h>
#include <math.h>

// ViT self-attention, B=8, N=2048, E=768, single head, fp32.
// Stage pipeline through __device__ global scratch (no allocations).
//
// 1) q = x@Wq+bq ; k = x@Wk+bk ; v = x@Wv+bv        (NN gemm, M=16384,N=768,K=768)
// 2) s = (q @ k^T) / sqrt(768)   per batch          (NT gemm, M=N=2048,K=768)
// 3) s = softmax(s, axis=-1)                        (row softmax, 2048 cols)
// 4) ao = s @ v                  per batch          (NN gemm, M=2048,N=768,K=2048)
// 5) out = ao @ Wo + bo                             (NN gemm, M=16384,N=768,K=768)

#define BM 128
#define BN 128
#define BK 32
#define TM 8
#define TN 8
#define NTHREADS 256

__device__ float g_q[8 * 2048 * 768];
__device__ float g_k[8 * 2048 * 768];
__device__ float g_v[8 * 2048 * 768];
__device__ float g_s[8 * 2048 * 2048];
__device__ float g_ao[8 * 2048 * 768];

// Generic tiled SGEMM.
//   BT=false: C[m,n] = alpha * sum_k A[m,k] * B[k,n]  (+ bias[n])
//   BT=true : C[m,n] = alpha * sum_k A[m,k] * B[n,k]  (+ bias[n])
// A: lda row stride, B: ldb row stride, C: ldc row stride.
// blockIdx.z selects batch via strideA/strideB/strideC element offsets.
// Requires: M % BM == 0, N % BN == 0, K % BK == 0, all pointers 16B aligned,
// lda/ldb/ldc % 4 == 0.
template <bool BT>
__global__ __launch_bounds__(NTHREADS)
void gemm_kernel(const float* __restrict__ A, int lda, long long strideA,
                 const float* __restrict__ B, int ldb, long long strideB,
                 float* __restrict__ C, int ldc, long long strideC,
                 int K, const float* __restrict__ bias, float alpha)
{
    __shared__ float As[BK][BM];
    __shared__ float Bs[BK][BN];

    const int tid = threadIdx.x;
    const int tx = tid & 15;        // 0..15  -> column group
    const int ty = tid >> 4;        // 0..15  -> row group
    const int m0 = blockIdx.y * BM;
    const int n0 = blockIdx.x * BN;

    A += (long long)blockIdx.z * strideA;
    B += (long long)blockIdx.z * strideB;
    C += (long long)blockIdx.z * strideC;

    float acc[TM][TN];
#pragma unroll
    for (int i = 0; i < TM; i++)
#pragma unroll
        for (int j = 0; j < TN; j++) acc[i][j] = 0.0f;

    const int arow = tid >> 3;         // 0..31
    const int acol = (tid & 7) * 4;    // 0,4,...,28

    for (int kt = 0; kt < K; kt += BK) {
        // ---- load A tile (BM x BK), store transposed As[k][m] ----
#pragma unroll
        for (int i = 0; i < 4; i++) {
            const int r = arow + 32 * i;  // 0..127
            const float4 v4 = *(const float4*)(A + (long long)(m0 + r) * lda + kt + acol);
            As[acol + 0][r] = v4.x;
            As[acol + 1][r] = v4.y;
            As[acol + 2][r] = v4.z;
            As[acol + 3][r] = v4.w;
        }
        if (!BT) {
            // ---- load B tile (BK x BN) direct: Bs[k][n] ----
            const int brow = tid >> 5;          // 0..7
            const int bcol = (tid & 31) * 4;    // 0..124
#pragma unroll
            for (int i = 0; i < 4; i++) {
                const int r = brow + 8 * i;     // 0..31
                const float4 v4 = *(const float4*)(B + (long long)(kt + r) * ldb + n0 + bcol);
                *(float4*)&Bs[r][bcol] = v4;
            }
        } else {
            // ---- load B tile (BN x BK), store transposed Bs[k][n] ----
#pragma unroll
            for (int i = 0; i < 4; i++) {
                const int r = arow + 32 * i;    // 0..127 (n index)
                const float4 v4 = *(const float4*)(B + (long long)(n0 + r) * ldb + kt + acol);
                Bs[acol + 0][r] = v4.x;
                Bs[acol + 1][r] = v4.y;
                Bs[acol + 2][r] = v4.z;
                Bs[acol + 3][r] = v4.w;
            }
        }
        __syncthreads();

#pragma unroll 8
        for (int kk = 0; kk < BK; kk++) {
            float a[TM], b[TN];
            *(float4*)&a[0] = *(const float4*)&As[kk][ty * TM + 0];
            *(float4*)&a[4] = *(const float4*)&As[kk][ty * TM + 4];
            *(float4*)&b[0] = *(const float4*)&Bs[kk][tx * TN + 0];
            *(float4*)&b[4] = *(const float4*)&Bs[kk][tx * TN + 4];
#pragma unroll
            for (int i = 0; i < TM; i++)
#pragma unroll
                for (int j = 0; j < TN; j++)
                    acc[i][j] = fmaf(a[i], b[j], acc[i][j]);
        }
        __syncthreads();
    }

    // ---- epilogue: scale, bias, store (float4) ----
    float bfrag[TN];
#pragma unroll
    for (int j = 0; j < TN; j++)
        bfrag[j] = bias ? bias[n0 + tx * TN + j] : 0.0f;

#pragma unroll
    for (int i = 0; i < TM; i++) {
        const long long m = m0 + ty * TM + i;
        float* crow = C + m * ldc + n0 + tx * TN;
#pragma unroll
        for (int j = 0; j < TN; j += 4) {
            float4 w;
            w.x = acc[i][j + 0] * alpha + bfrag[j + 0];
            w.y = acc[i][j + 1] * alpha + bfrag[j + 1];
            w.z = acc[i][j + 2] * alpha + bfrag[j + 2];
            w.w = acc[i][j + 3] * alpha + bfrag[j + 3];
            *(float4*)(crow + j) = w;
        }
    }
}

// Row softmax over ncols = 2048, one block (256 threads) per row.
__global__ __launch_bounds__(256)
void softmax_kernel(float* __restrict__ S)
{
    __shared__ float red[8];
    const long long row = blockIdx.x;
    float* p = S + row * 2048ll;
    const int tid = threadIdx.x;
    const int lane = tid & 31, warp = tid >> 5;

    float v[8];
#pragma unroll
    for (int i = 0; i < 8; i++) v[i] = p[tid + 256 * i];

    // block max
    float m = v[0];
#pragma unroll
    for (int i = 1; i < 8; i++) m = fmaxf(m, v[i]);
#pragma unroll
    for (int o = 16; o > 0; o >>= 1) m = fmaxf(m, __shfl_xor_sync(0xffffffffu, m, o));
    if (lane == 0) red[warp] = m;
    __syncthreads();
    float bm = red[0];
#pragma unroll
    for (int w = 1; w < 8; w++) bm = fmaxf(bm, red[w]);

    // exp + block sum
    float s = 0.0f;
#pragma unroll
    for (int i = 0; i < 8; i++) { v[i] = __expf(v[i] - bm); s += v[i]; }
#pragma unroll
    for (int o = 16; o > 0; o >>= 1) s += __shfl_xor_sync(0xffffffffu, s, o);
    __syncthreads();   // red[] reuse guard
    if (lane == 0) red[warp] = s;
    __syncthreads();
    float bs = red[0];
#pragma unroll
    for (int w = 1; w < 8; w++) bs += red[w];

    const float inv = 1.0f / bs;
#pragma unroll
    for (int i = 0; i < 8; i++) p[tid + 256 * i] = v[i] * inv;
}

extern "C" void kernel_launch(void* const* d_in, const int* in_sizes, int n_in,
                              void* d_out, int out_size)
{
    const float* x  = (const float*)d_in[0];
    const float* Wq = (const float*)d_in[1];
    const float* bq = (const float*)d_in[2];
    const float* Wk = (const float*)d_in[3];
    const float* bk = (const float*)d_in[4];
    const float* Wv = (const float*)d_in[5];
    const float* bv = (const float*)d_in[6];
    const float* Wo = (const float*)d_in[7];
    const float* bo = (const float*)d_in[8];
    float* out = (float*)d_out;

    float *q, *k, *v, *s, *ao;
    cudaGetSymbolAddress((void**)&q,  g_q);
    cudaGetSymbolAddress((void**)&k,  g_k);
    cudaGetSymbolAddress((void**)&v,  g_v);
    cudaGetSymbolAddress((void**)&s,  g_s);
    cudaGetSymbolAddress((void**)&ao, g_ao);

    const int B = 8, N = 2048, E = 768;
    const int M = B * N;                       // 16384
    const long long sNE = (long long)N * E;    // 2048*768
    const long long sNN = (long long)N * N;    // 2048*2048
    const float scale = 1.0f / sqrtf((float)E);

    dim3 blk(NTHREADS);

    // 1) Q/K/V projections
    dim3 gProj(E / BN, M / BM, 1);  // (6, 128, 1)
    gemm_kernel<false><<<gProj, blk>>>(x, E, 0, Wq, E, 0, q, E, 0, E, bq, 1.0f);
    gemm_kernel<false><<<gProj, blk>>>(x, E, 0, Wk, E, 0, k, E, 0, E, bk, 1.0f);
    gemm_kernel<false><<<gProj, blk>>>(x, E, 0, Wv, E, 0, v, E, 0, E, bv, 1.0f);

    // 2) scores = q @ k^T * scale  (per batch)
    dim3 gS(N / BN, N / BM, B);     // (16, 16, 8)
    gemm_kernel<true><<<gS, blk>>>(q, E, sNE, k, E, sNE, s, N, sNN, E, nullptr, scale);

    // 3) softmax over last dim
    softmax_kernel<<<B * N, 256>>>(s);

    // 4) ao = attn @ v (per batch)
    dim3 gAV(E / BN, N / BM, B);    // (6, 16, 8)
    gemm_kernel<false><<<gAV, blk>>>(s, N, sNN, v, E, sNE, ao, E, sNE, N, nullptr, 1.0f);

    // 5) out = ao @ Wo + bo
    gemm_kernel<false><<<gProj, blk>>>(ao, E, 0, Wo, E, 0, out, E, 0, E, bo, 1.0f);
}

// round 6
// speedup vs baseline: 1.8713x; 1.8713x over previous
#include <cuda_runtime.h>
#include <cuda_bf16.h>
#include <cstdint>
#include <math.h>

// ViT self-attention, B=8, N=2048, E=768, single head, fp32 in/out.
// All GEMMs on warp-level tensor cores (mma.sync m16n8k16 bf16, fp32 accum)
// with split-bf16 (hi+lo) emulated fp32: D += Ahi*Bhi + Ahi*Blo + Alo*Bhi.
// (tcgen05 is unavailable: harness compiles for plain sm_103, not sm_103a.)
//
// Stages:
//  P0: split/transpose weights -> WT_hi/lo[f][e] bf16 ; split x -> x_hi/lo
//  S1: q = x@Wq^T(+bq), k = x@Wk^T(+bk)   -> hi/lo bf16 [16384,768]
//      vT = WvT@x^T(+bv per-row)          -> hi/lo bf16 [8][768][2048]
//  S2: s = (q @ k^T) * 1/sqrt(768)        -> fp32 [8][2048][2048]
//  S3: softmax rows, fused conversion     -> attn hi/lo bf16
//  S4: ao = attn @ vT^T                   -> hi/lo bf16 [16384,768]
//  S5: out = ao@Wo^T + bo                 -> fp32 d_out

// ---------------- dims / scratch ----------------
static constexpr int BB = 8, NN = 2048, EE = 768;
static constexpr int MM = BB * NN;                  // 16384
static constexpr long long sNE = (long long)NN * EE;
static constexpr long long sNN = (long long)NN * NN;
static constexpr int WW = EE * EE;

__device__ __nv_bfloat16 g_xhi[MM * EE],  g_xlo[MM * EE];
__device__ __nv_bfloat16 g_wthi[4 * WW],  g_wtlo[4 * WW];
__device__ __nv_bfloat16 g_qhi[MM * EE],  g_qlo[MM * EE];
__device__ __nv_bfloat16 g_khi[MM * EE],  g_klo[MM * EE];
__device__ __nv_bfloat16 g_vthi[BB * EE * NN], g_vtlo[BB * EE * NN];
__device__ float         g_s[BB * sNN];
__device__ __nv_bfloat16 g_athi[BB * sNN], g_atlo[BB * sNN];
__device__ __nv_bfloat16 g_aohi[MM * EE], g_aolo[MM * EE];

// ---------------- PTX helpers ----------------
__device__ __forceinline__ uint32_t smem_u32(const void* p) {
    uint32_t a;
    asm("{ .reg .u64 t; cvta.to.shared.u64 t, %1; cvt.u32.u64 %0, t; }" : "=r"(a) : "l"(p));
    return a;
}
__device__ __forceinline__ void ldsm_x4(uint32_t* r, uint32_t addr) {
    asm volatile("ldmatrix.sync.aligned.m8n8.x4.shared.b16 {%0,%1,%2,%3}, [%4];"
                 : "=r"(r[0]), "=r"(r[1]), "=r"(r[2]), "=r"(r[3]) : "r"(addr));
}
__device__ __forceinline__ void mma16816(float* d, const uint32_t* a, const uint32_t* b) {
    asm volatile(
        "mma.sync.aligned.m16n8k16.row.col.f32.bf16.bf16.f32 "
        "{%0,%1,%2,%3}, {%4,%5,%6,%7}, {%8,%9}, {%0,%1,%2,%3};"
        : "+f"(d[0]), "+f"(d[1]), "+f"(d[2]), "+f"(d[3])
        : "r"(a[0]), "r"(a[1]), "r"(a[2]), "r"(a[3]), "r"(b[0]), "r"(b[1]));
}

// ---------------- smem layout ----------------
// Tiles 128 rows x 32 bf16, padded row stride 40 bf16 (80B, 16B-aligned,
// conflict-free ldmatrix phases: word offsets r*20 mod 32 partition the banks).
static constexpr int LDT = 80;                 // bytes per padded row
static constexpr int SA_HI = 0;
static constexpr int SA_LO = 128 * LDT;        // 10240
static constexpr int SB_HI = 2 * 128 * LDT;    // 20480
static constexpr int SB_LO = 3 * 128 * LDT;    // 30720
static constexpr int SM_BYTES = 4 * 128 * LDT; // 40960

// ---------------- tensor-core GEMM ----------------
// C[m,n] = alpha * sum_k A[m,k]*B[n,k] (+ bias), A/B split hi/lo bf16 K-major.
// CTA tile 128x128, BK=32. 8 warps: 2(M)x4(N), warp tile 64x32.
// Grid: (N/128, M/128, batch).
__global__ void __launch_bounds__(256, 2)
mma_gemm(const __nv_bfloat16* __restrict__ Ahi, const __nv_bfloat16* __restrict__ Alo,
         long long lda, long long strideA,
         const __nv_bfloat16* __restrict__ Bhi, const __nv_bfloat16* __restrict__ Blo,
         long long ldb, long long strideB,
         float* __restrict__ Cf32,
         __nv_bfloat16* __restrict__ Chi, __nv_bfloat16* __restrict__ Clo,
         long long ldc, long long strideC,
         int K, const float* __restrict__ bias, int bias_row, float alpha)
{
    __shared__ __align__(16) char sm[SM_BYTES];
    const uint32_t smb = smem_u32(sm);
    const int tid = threadIdx.x, wid = tid >> 5, lane = tid & 31;
    const int m0 = blockIdx.y * 128, n0 = blockIdx.x * 128;
    const long long z = blockIdx.z;
    const int m_w = (wid >> 2) * 64;   // warp M offset (0,64)
    const int n_w = (wid & 3) * 32;    // warp N offset (0,32,64,96)

    Ahi += z * strideA; Alo += z * strideA;
    Bhi += z * strideB; Blo += z * strideB;

    // ldmatrix base addresses (bytes), add kk*2 per k-half.
    uint32_t aHi[4], aLo[4], bHi[2], bLo[2];
    {
        const uint32_t arow = m_w + (lane & 15);
        const uint32_t aoff = (lane >> 4) * 16;
#pragma unroll
        for (int i = 0; i < 4; i++) {
            const uint32_t o = (arow + i * 16) * LDT + aoff;
            aHi[i] = smb + SA_HI + o;
            aLo[i] = smb + SA_LO + o;
        }
        const uint32_t brow = n_w + (lane & 7) + ((lane >> 4) & 1) * 8;
        const uint32_t boff = ((lane >> 3) & 1) * 16;
#pragma unroll
        for (int p = 0; p < 2; p++) {
            const uint32_t o = (brow + p * 16) * LDT + boff;
            bHi[p] = smb + SB_HI + o;
            bLo[p] = smb + SB_LO + o;
        }
    }

    float acc[4][4][4];
#pragma unroll
    for (int i = 0; i < 4; i++)
#pragma unroll
        for (int j = 0; j < 4; j++)
#pragma unroll
            for (int c = 0; c < 4; c++) acc[i][j][c] = 0.0f;

    const int r_ld = tid >> 2;            // 0..63
    const int c_ld = (tid & 3) * 16;      // byte chunk within row

    for (int kt = 0; kt < K; kt += 32) {
        // ---- load tiles: 128 rows x 32 bf16 (64B) hi+lo for A and B ----
#pragma unroll
        for (int it = 0; it < 2; it++) {
            const int r = r_ld + it * 64;
            const uint32_t so = (uint32_t)(r * LDT + c_ld);
            const long long ga = (long long)(m0 + r) * lda + kt + (c_ld >> 1);
            const long long gb = (long long)(n0 + r) * ldb + kt + (c_ld >> 1);
            *(uint4*)(sm + SA_HI + so) = *(const uint4*)(Ahi + ga);
            *(uint4*)(sm + SA_LO + so) = *(const uint4*)(Alo + ga);
            *(uint4*)(sm + SB_HI + so) = *(const uint4*)(Bhi + gb);
            *(uint4*)(sm + SB_LO + so) = *(const uint4*)(Blo + gb);
        }
        __syncthreads();

#pragma unroll
        for (int kk = 0; kk < 2; kk++) {
            const uint32_t k2 = kk * 32;   // 16 bf16 = 32 bytes
            uint32_t af[4][4], bf[2][4];
            // pass 1: Ahi * Bhi
#pragma unroll
            for (int i = 0; i < 4; i++) ldsm_x4(af[i], aHi[i] + k2);
#pragma unroll
            for (int p = 0; p < 2; p++) ldsm_x4(bf[p], bHi[p] + k2);
#pragma unroll
            for (int i = 0; i < 4; i++)
#pragma unroll
                for (int j = 0; j < 4; j++)
                    mma16816(acc[i][j], af[i], &bf[j >> 1][(j & 1) * 2]);
            // pass 2: Ahi * Blo
#pragma unroll
            for (int p = 0; p < 2; p++) ldsm_x4(bf[p], bLo[p] + k2);
#pragma unroll
            for (int i = 0; i < 4; i++)
#pragma unroll
                for (int j = 0; j < 4; j++)
                    mma16816(acc[i][j], af[i], &bf[j >> 1][(j & 1) * 2]);
            // pass 3: Alo * Bhi
#pragma unroll
            for (int i = 0; i < 4; i++) ldsm_x4(af[i], aLo[i] + k2);
#pragma unroll
            for (int p = 0; p < 2; p++) ldsm_x4(bf[p], bHi[p] + k2);
#pragma unroll
            for (int i = 0; i < 4; i++)
#pragma unroll
                for (int j = 0; j < 4; j++)
                    mma16816(acc[i][j], af[i], &bf[j >> 1][(j & 1) * 2]);
        }
        __syncthreads();
    }

    // ---- epilogue ----
#pragma unroll
    for (int i = 0; i < 4; i++) {
#pragma unroll
        for (int h = 0; h < 2; h++) {
            const int row = m0 + m_w + i * 16 + (lane >> 2) + h * 8;
            const float brow = (bias && bias_row) ? bias[row] : 0.0f;
            const long long rbase = z * strideC + (long long)row * ldc;
#pragma unroll
            for (int j = 0; j < 4; j++) {
                const int col = n0 + n_w + j * 8 + 2 * (lane & 3);
                float v0 = acc[i][j][h * 2 + 0] * alpha;
                float v1 = acc[i][j][h * 2 + 1] * alpha;
                if (bias) {
                    if (bias_row) { v0 += brow; v1 += brow; }
                    else          { v0 += bias[col]; v1 += bias[col + 1]; }
                }
                if (Cf32) {
                    float2 w; w.x = v0; w.y = v1;
                    *(float2*)(Cf32 + rbase + col) = w;
                }
                if (Chi) {
                    const __nv_bfloat16 h0 = __float2bfloat16(v0);
                    const __nv_bfloat16 h1 = __float2bfloat16(v1);
                    *(__nv_bfloat162*)(Chi + rbase + col) = __halves2bfloat162(h0, h1);
                    const __nv_bfloat16 l0 = __float2bfloat16(v0 - __bfloat162float(h0));
                    const __nv_bfloat16 l1 = __float2bfloat16(v1 - __bfloat162float(h1));
                    *(__nv_bfloat162*)(Clo + rbase + col) = __halves2bfloat162(l0, l1);
                }
            }
        }
    }
}

// ---------------- prep kernels ----------------
// Transpose + split the 4 weight matrices: WT_hi/lo[f][e] = split(W[e][f]).
__global__ void __launch_bounds__(256)
wprep(const float* __restrict__ W0, const float* __restrict__ W1,
      const float* __restrict__ W2, const float* __restrict__ W3,
      __nv_bfloat16* __restrict__ hi, __nv_bfloat16* __restrict__ lo)
{
    __shared__ float t[32][33];
    const int zi = blockIdx.z;
    const float* W = (zi == 0) ? W0 : (zi == 1) ? W1 : (zi == 2) ? W2 : W3;
    __nv_bfloat16* H = hi + (long long)zi * WW;
    __nv_bfloat16* L = lo + (long long)zi * WW;
    const int bx = blockIdx.x * 32, by = blockIdx.y * 32;
    const int tx = threadIdx.x, ty = threadIdx.y;
#pragma unroll
    for (int i = 0; i < 32; i += 8)
        t[ty + i][tx] = W[(long long)(by + ty + i) * EE + bx + tx];
    __syncthreads();
#pragma unroll
    for (int i = 0; i < 32; i += 8) {
        const float v = t[tx][ty + i];
        const __nv_bfloat16 h = __float2bfloat16(v);
        const long long o = (long long)(bx + ty + i) * EE + by + tx;
        H[o] = h;
        L[o] = __float2bfloat16(v - __bfloat162float(h));
    }
}

// Split x into hi/lo bf16 (vectorized).
__global__ void __launch_bounds__(256)
xsplit(const float* __restrict__ x, __nv_bfloat16* __restrict__ hi,
       __nv_bfloat16* __restrict__ lo, int n4)
{
    const int i = blockIdx.x * blockDim.x + threadIdx.x;
    if (i >= n4) return;
    const float4 v = ((const float4*)x)[i];
    __nv_bfloat16 h0 = __float2bfloat16(v.x), h1 = __float2bfloat16(v.y);
    __nv_bfloat16 h2 = __float2bfloat16(v.z), h3 = __float2bfloat16(v.w);
    ((__nv_bfloat162*)hi)[2 * i]     = __halves2bfloat162(h0, h1);
    ((__nv_bfloat162*)hi)[2 * i + 1] = __halves2bfloat162(h2, h3);
    __nv_bfloat16 l0 = __float2bfloat16(v.x - __bfloat162float(h0));
    __nv_bfloat16 l1 = __float2bfloat16(v.y - __bfloat162float(h1));
    __nv_bfloat16 l2 = __float2bfloat16(v.z - __bfloat162float(h2));
    __nv_bfloat16 l3 = __float2bfloat16(v.w - __bfloat162float(h3));
    ((__nv_bfloat162*)lo)[2 * i]     = __halves2bfloat162(l0, l1);
    ((__nv_bfloat162*)lo)[2 * i + 1] = __halves2bfloat162(l2, l3);
}

// Row softmax (2048 cols) fused with hi/lo bf16 conversion.
__global__ void __launch_bounds__(256)
softmax_kernel(const float* __restrict__ S, __nv_bfloat16* __restrict__ Ahi,
               __nv_bfloat16* __restrict__ Alo)
{
    __shared__ float red[8];
    const long long row = blockIdx.x;
    const float* p = S + row * 2048ll;
    const int tid = threadIdx.x, lane = tid & 31, warp = tid >> 5;

    float v[8];
#pragma unroll
    for (int i = 0; i < 8; i++) v[i] = p[tid + 256 * i];

    float m = v[0];
#pragma unroll
    for (int i = 1; i < 8; i++) m = fmaxf(m, v[i]);
#pragma unroll
    for (int o = 16; o > 0; o >>= 1) m = fmaxf(m, __shfl_xor_sync(0xffffffffu, m, o));
    if (lane == 0) red[warp] = m;
    __syncthreads();
    float bm = red[0];
#pragma unroll
    for (int w = 1; w < 8; w++) bm = fmaxf(bm, red[w]);

    float s = 0.0f;
#pragma unroll
    for (int i = 0; i < 8; i++) { v[i] = __expf(v[i] - bm); s += v[i]; }
#pragma unroll
    for (int o = 16; o > 0; o >>= 1) s += __shfl_xor_sync(0xffffffffu, s, o);
    __syncthreads();
    if (lane == 0) red[warp] = s;
    __syncthreads();
    float bs = red[0];
#pragma unroll
    for (int w = 1; w < 8; w++) bs += red[w];

    const float inv = 1.0f / bs;
#pragma unroll
    for (int i = 0; i < 8; i++) {
        const float o = v[i] * inv;
        const long long idx = row * 2048ll + tid + 256 * i;
        const __nv_bfloat16 h = __float2bfloat16(o);
        Ahi[idx] = h;
        Alo[idx] = __float2bfloat16(o - __bfloat162float(h));
    }
}

// ---------------- launch ----------------
extern "C" void kernel_launch(void* const* d_in, const int* in_sizes, int n_in,
                              void* d_out, int out_size)
{
    const float* x  = (const float*)d_in[0];
    const float* Wq = (const float*)d_in[1];
    const float* bq = (const float*)d_in[2];
    const float* Wk = (const float*)d_in[3];
    const float* bk = (const float*)d_in[4];
    const float* Wv = (const float*)d_in[5];
    const float* bv = (const float*)d_in[6];
    const float* Wo = (const float*)d_in[7];
    const float* bo = (const float*)d_in[8];
    float* out = (float*)d_out;

    __nv_bfloat16 *xhi, *xlo, *wthi, *wtlo, *qhi, *qlo, *khi, *klo;
    __nv_bfloat16 *vthi, *vtlo, *athi, *atlo, *aohi, *aolo;
    float* s;
    cudaGetSymbolAddress((void**)&xhi, g_xhi);   cudaGetSymbolAddress((void**)&xlo, g_xlo);
    cudaGetSymbolAddress((void**)&wthi, g_wthi); cudaGetSymbolAddress((void**)&wtlo, g_wtlo);
    cudaGetSymbolAddress((void**)&qhi, g_qhi);   cudaGetSymbolAddress((void**)&qlo, g_qlo);
    cudaGetSymbolAddress((void**)&khi, g_khi);   cudaGetSymbolAddress((void**)&klo, g_klo);
    cudaGetSymbolAddress((void**)&vthi, g_vthi); cudaGetSymbolAddress((void**)&vtlo, g_vtlo);
    cudaGetSymbolAddress((void**)&s, g_s);
    cudaGetSymbolAddress((void**)&athi, g_athi); cudaGetSymbolAddress((void**)&atlo, g_atlo);
    cudaGetSymbolAddress((void**)&aohi, g_aohi); cudaGetSymbolAddress((void**)&aolo, g_aolo);

    const float scale = 1.0f / sqrtf((float)EE);

    // P0: prep
    wprep<<<dim3(24, 24, 4), dim3(32, 8)>>>(Wq, Wk, Wv, Wo, wthi, wtlo);
    const int n4 = MM * EE / 4;
    xsplit<<<(n4 + 255) / 256, 256>>>(x, xhi, xlo, n4);

    // S1: q, k projections  (M=16384, N=768, K=768)
    mma_gemm<<<dim3(6, 128, 1), 256>>>(
        xhi, xlo, EE, 0, wthi + 0 * WW, wtlo + 0 * WW, EE, 0,
        nullptr, qhi, qlo, EE, 0, EE, bq, 0, 1.0f);
    mma_gemm<<<dim3(6, 128, 1), 256>>>(
        xhi, xlo, EE, 0, wthi + 1 * WW, wtlo + 1 * WW, EE, 0,
        nullptr, khi, klo, EE, 0, EE, bk, 0, 1.0f);
    // S1v: vT[f][t] per batch  (A=WvT [768,768], B=x rows of batch, bias per-row)
    mma_gemm<<<dim3(16, 6, 8), 256>>>(
        wthi + 2 * WW, wtlo + 2 * WW, EE, 0, xhi, xlo, EE, sNE,
        nullptr, vthi, vtlo, NN, (long long)EE * NN, EE, bv, 1, 1.0f);

    // S2: scores = q @ k^T * scale per batch  (M=N=2048, K=768)
    mma_gemm<<<dim3(16, 16, 8), 256>>>(
        qhi, qlo, EE, sNE, khi, klo, EE, sNE,
        s, nullptr, nullptr, NN, sNN, EE, nullptr, 0, scale);

    // S3: softmax + bf16 split
    softmax_kernel<<<MM, 256>>>(s, athi, atlo);

    // S4: ao = attn @ v per batch  (M=2048, N=768, K=2048), B = vT K-major
    mma_gemm<<<dim3(6, 16, 8), 256>>>(
        athi, atlo, NN, sNN, vthi, vtlo, NN, (long long)EE * NN,
        nullptr, aohi, aolo, EE, sNE, NN, nullptr, 0, 1.0f);

    // S5: out = ao @ Wo^T + bo
    mma_gemm<<<dim3(6, 128, 1), 256>>>(
        aohi, aolo, EE, 0, wthi + 3 * WW, wtlo + 3 * WW, EE, 0,
        out, nullptr, nullptr, EE, 0, EE, bo, 0, 1.0f);
}

// round 7
// speedup vs baseline: 2.7787x; 1.4849x over previous
#include <cuda_runtime.h>
#include <cuda_bf16.h>
#include <cstdint>
#include <math.h>

// ViT self-attention, B=8, N=2048, E=768, single head, fp32 in/out.
// All GEMMs on warp-level tensor cores (mma.sync m16n8k16 bf16, fp32 accum)
// with split-bf16 (hi+lo) emulated fp32: D += Ahi*Bhi + Ahi*Blo + Alo*Bhi.
// R7: cp.async 2-stage double-buffered mainloop + ldmatrix dedup (12/k-half).

// ---------------- dims / scratch ----------------
static constexpr int BB = 8, NN = 2048, EE = 768;
static constexpr int MM = BB * NN;                  // 16384
static constexpr long long sNE = (long long)NN * EE;
static constexpr long long sNN = (long long)NN * NN;
static constexpr int WW = EE * EE;

__device__ __nv_bfloat16 g_xhi[MM * EE],  g_xlo[MM * EE];
__device__ __nv_bfloat16 g_wthi[4 * WW],  g_wtlo[4 * WW];
__device__ __nv_bfloat16 g_qhi[MM * EE],  g_qlo[MM * EE];
__device__ __nv_bfloat16 g_khi[MM * EE],  g_klo[MM * EE];
__device__ __nv_bfloat16 g_vthi[BB * EE * NN], g_vtlo[BB * EE * NN];
__device__ float         g_s[BB * sNN];
__device__ __nv_bfloat16 g_athi[BB * sNN], g_atlo[BB * sNN];
__device__ __nv_bfloat16 g_aohi[MM * EE], g_aolo[MM * EE];

// ---------------- PTX helpers ----------------
__device__ __forceinline__ uint32_t smem_u32(const void* p) {
    uint32_t a;
    asm("{ .reg .u64 t; cvta.to.shared.u64 t, %1; cvt.u32.u64 %0, t; }" : "=r"(a) : "l"(p));
    return a;
}
__device__ __forceinline__ void ldsm_x4(uint32_t* r, uint32_t addr) {
    asm volatile("ldmatrix.sync.aligned.m8n8.x4.shared.b16 {%0,%1,%2,%3}, [%4];"
                 : "=r"(r[0]), "=r"(r[1]), "=r"(r[2]), "=r"(r[3]) : "r"(addr));
}
__device__ __forceinline__ void mma16816(float* d, const uint32_t* a, const uint32_t* b) {
    asm volatile(
        "mma.sync.aligned.m16n8k16.row.col.f32.bf16.bf16.f32 "
        "{%0,%1,%2,%3}, {%4,%5,%6,%7}, {%8,%9}, {%0,%1,%2,%3};"
        : "+f"(d[0]), "+f"(d[1]), "+f"(d[2]), "+f"(d[3])
        : "r"(a[0]), "r"(a[1]), "r"(a[2]), "r"(a[3]), "r"(b[0]), "r"(b[1]));
}
__device__ __forceinline__ void cp_async16(uint32_t saddr, const void* g) {
    asm volatile("cp.async.cg.shared.global [%0], [%1], 16;" :: "r"(saddr), "l"(g));
}
#define CP_COMMIT() asm volatile("cp.async.commit_group;" ::: "memory")
#define CP_WAIT(n)  asm volatile("cp.async.wait_group %0;" :: "n"(n) : "memory")

// ---------------- smem layout ----------------
// Per stage: 4 tiles of 128 rows x 32 bf16, padded row stride 40 bf16 (80B).
static constexpr int LDT = 80;
static constexpr int SA_HI = 0;
static constexpr int SA_LO = 128 * LDT;
static constexpr int SB_HI = 2 * 128 * LDT;
static constexpr int SB_LO = 3 * 128 * LDT;
static constexpr int STAGE = 4 * 128 * LDT;     // 40960
static constexpr int SM_BYTES = 2 * STAGE;      // 81920 (dynamic)

// ---------------- tensor-core GEMM ----------------
// C[m,n] = alpha * sum_k A[m,k]*B[n,k] (+ bias), A/B split hi/lo bf16 K-major.
// CTA tile 128x128, BK=32, 2-stage cp.async pipeline.
// 8 warps: 2(M)x4(N), warp tile 64x32. Grid: (N/128, M/128, batch).
__global__ void __launch_bounds__(256, 2)
mma_gemm(const __nv_bfloat16* __restrict__ Ahi, const __nv_bfloat16* __restrict__ Alo,
         long long lda, long long strideA,
         const __nv_bfloat16* __restrict__ Bhi, const __nv_bfloat16* __restrict__ Blo,
         long long ldb, long long strideB,
         float* __restrict__ Cf32,
         __nv_bfloat16* __restrict__ Chi, __nv_bfloat16* __restrict__ Clo,
         long long ldc, long long strideC,
         int K, const float* __restrict__ bias, int bias_row, float alpha)
{
    extern __shared__ __align__(16) char sm[];
    const uint32_t smb = smem_u32(sm);
    const int tid = threadIdx.x, wid = tid >> 5, lane = tid & 31;
    const int m0 = blockIdx.y * 128, n0 = blockIdx.x * 128;
    const long long z = blockIdx.z;
    const int m_w = (wid >> 2) * 64;   // warp M offset (0,64)
    const int n_w = (wid & 3) * 32;    // warp N offset (0,32,64,96)

    Ahi += z * strideA; Alo += z * strideA;
    Bhi += z * strideB; Blo += z * strideB;

    // ldmatrix base offsets within a stage (bytes); add stage base + kk*32.
    uint32_t aOffH[4], aOffL[4], bOffH[2], bOffL[2];
    {
        const uint32_t arow = m_w + (lane & 15);
        const uint32_t aoff = (lane >> 4) * 16;
#pragma unroll
        for (int i = 0; i < 4; i++) {
            const uint32_t o = (arow + i * 16) * LDT + aoff;
            aOffH[i] = SA_HI + o;
            aOffL[i] = SA_LO + o;
        }
        const uint32_t brow = n_w + (lane & 7) + ((lane >> 4) & 1) * 8;
        const uint32_t boff = ((lane >> 3) & 1) * 16;
#pragma unroll
        for (int p = 0; p < 2; p++) {
            const uint32_t o = (brow + p * 16) * LDT + boff;
            bOffH[p] = SB_HI + o;
            bOffL[p] = SB_LO + o;
        }
    }

    float acc[4][4][4];
#pragma unroll
    for (int i = 0; i < 4; i++)
#pragma unroll
        for (int j = 0; j < 4; j++)
#pragma unroll
            for (int c = 0; c < 4; c++) acc[i][j][c] = 0.0f;

    const int r_ld = tid >> 2;            // 0..63
    const int c_ld = (tid & 3) * 16;      // byte chunk within row (0..48)
    const int gcol = c_ld >> 1;           // bf16 column offset (0..24)

    const int nch = K >> 5;

    // issue async loads for chunk ck into stage st
    auto issue = [&](int ck, int st) {
        const int kt = ck << 5;
        const uint32_t sb = smb + st * STAGE;
#pragma unroll
        for (int it = 0; it < 2; it++) {
            const int r = r_ld + it * 64;
            const uint32_t so = (uint32_t)(r * LDT + c_ld);
            const long long ga = (long long)(m0 + r) * lda + kt + gcol;
            const long long gb = (long long)(n0 + r) * ldb + kt + gcol;
            cp_async16(sb + SA_HI + so, Ahi + ga);
            cp_async16(sb + SA_LO + so, Alo + ga);
            cp_async16(sb + SB_HI + so, Bhi + gb);
            cp_async16(sb + SB_LO + so, Blo + gb);
        }
        CP_COMMIT();
    };

    issue(0, 0);

    for (int ck = 0; ck < nch; ck++) {
        const int st = ck & 1;
        if (ck + 1 < nch) {
            issue(ck + 1, st ^ 1);
            CP_WAIT(1);
        } else {
            CP_WAIT(0);
        }
        __syncthreads();

        const uint32_t sb = smb + st * STAGE;
#pragma unroll
        for (int kk = 0; kk < 2; kk++) {
            const uint32_t k2 = kk * 32;
            uint32_t afH[4][4], afL[4][4], bf[2][4];
            // load all A fragments once; B-hi once, B-lo once (12 ldsm total)
#pragma unroll
            for (int i = 0; i < 4; i++) ldsm_x4(afH[i], sb + aOffH[i] + k2);
#pragma unroll
            for (int p = 0; p < 2; p++) ldsm_x4(bf[p], sb + bOffH[p] + k2);
            // pass 1: Ahi * Bhi
#pragma unroll
            for (int i = 0; i < 4; i++)
#pragma unroll
                for (int j = 0; j < 4; j++)
                    mma16816(acc[i][j], afH[i], &bf[j >> 1][(j & 1) * 2]);
            // pass 2: Alo * Bhi (B-hi still resident)
#pragma unroll
            for (int i = 0; i < 4; i++) ldsm_x4(afL[i], sb + aOffL[i] + k2);
#pragma unroll
            for (int i = 0; i < 4; i++)
#pragma unroll
                for (int j = 0; j < 4; j++)
                    mma16816(acc[i][j], afL[i], &bf[j >> 1][(j & 1) * 2]);
            // pass 3: Ahi * Blo (A-hi still resident)
#pragma unroll
            for (int p = 0; p < 2; p++) ldsm_x4(bf[p], sb + bOffL[p] + k2);
#pragma unroll
            for (int i = 0; i < 4; i++)
#pragma unroll
                for (int j = 0; j < 4; j++)
                    mma16816(acc[i][j], afH[i], &bf[j >> 1][(j & 1) * 2]);
        }
        __syncthreads();
    }

    // ---- epilogue ----
#pragma unroll
    for (int i = 0; i < 4; i++) {
#pragma unroll
        for (int h = 0; h < 2; h++) {
            const int row = m0 + m_w + i * 16 + (lane >> 2) + h * 8;
            const float brow = (bias && bias_row) ? bias[row] : 0.0f;
            const long long rbase = z * strideC + (long long)row * ldc;
#pragma unroll
            for (int j = 0; j < 4; j++) {
                const int col = n0 + n_w + j * 8 + 2 * (lane & 3);
                float v0 = acc[i][j][h * 2 + 0] * alpha;
                float v1 = acc[i][j][h * 2 + 1] * alpha;
                if (bias) {
                    if (bias_row) { v0 += brow; v1 += brow; }
                    else          { v0 += bias[col]; v1 += bias[col + 1]; }
                }
                if (Cf32) {
                    float2 w; w.x = v0; w.y = v1;
                    *(float2*)(Cf32 + rbase + col) = w;
                }
                if (Chi) {
                    const __nv_bfloat16 h0 = __float2bfloat16(v0);
                    const __nv_bfloat16 h1 = __float2bfloat16(v1);
                    *(__nv_bfloat162*)(Chi + rbase + col) = __halves2bfloat162(h0, h1);
                    const __nv_bfloat16 l0 = __float2bfloat16(v0 - __bfloat162float(h0));
                    const __nv_bfloat16 l1 = __float2bfloat16(v1 - __bfloat162float(h1));
                    *(__nv_bfloat162*)(Clo + rbase + col) = __halves2bfloat162(l0, l1);
                }
            }
        }
    }
}

// ---------------- prep kernels ----------------
__global__ void __launch_bounds__(256)
wprep(const float* __restrict__ W0, const float* __restrict__ W1,
      const float* __restrict__ W2, const float* __restrict__ W3,
      __nv_bfloat16* __restrict__ hi, __nv_bfloat16* __restrict__ lo)
{
    __shared__ float t[32][33];
    const int zi = blockIdx.z;
    const float* W = (zi == 0) ? W0 : (zi == 1) ? W1 : (zi == 2) ? W2 : W3;
    __nv_bfloat16* H = hi + (long long)zi * WW;
    __nv_bfloat16* L = lo + (long long)zi * WW;
    const int bx = blockIdx.x * 32, by = blockIdx.y * 32;
    const int tx = threadIdx.x, ty = threadIdx.y;
#pragma unroll
    for (int i = 0; i < 32; i += 8)
        t[ty + i][tx] = W[(long long)(by + ty + i) * EE + bx + tx];
    __syncthreads();
#pragma unroll
    for (int i = 0; i < 32; i += 8) {
        const float v = t[tx][ty + i];
        const __nv_bfloat16 h = __float2bfloat16(v);
        const long long o = (long long)(bx + ty + i) * EE + by + tx;
        H[o] = h;
        L[o] = __float2bfloat16(v - __bfloat162float(h));
    }
}

__global__ void __launch_bounds__(256)
xsplit(const float* __restrict__ x, __nv_bfloat16* __restrict__ hi,
       __nv_bfloat16* __restrict__ lo, int n4)
{
    const int i = blockIdx.x * blockDim.x + threadIdx.x;
    if (i >= n4) return;
    const float4 v = ((const float4*)x)[i];
    __nv_bfloat16 h0 = __float2bfloat16(v.x), h1 = __float2bfloat16(v.y);
    __nv_bfloat16 h2 = __float2bfloat16(v.z), h3 = __float2bfloat16(v.w);
    ((__nv_bfloat162*)hi)[2 * i]     = __halves2bfloat162(h0, h1);
    ((__nv_bfloat162*)hi)[2 * i + 1] = __halves2bfloat162(h2, h3);
    __nv_bfloat16 l0 = __float2bfloat16(v.x - __bfloat162float(h0));
    __nv_bfloat16 l1 = __float2bfloat16(v.y - __bfloat162float(h1));
    __nv_bfloat16 l2 = __float2bfloat16(v.z - __bfloat162float(h2));
    __nv_bfloat16 l3 = __float2bfloat16(v.w - __bfloat162float(h3));
    ((__nv_bfloat162*)lo)[2 * i]     = __halves2bfloat162(l0, l1);
    ((__nv_bfloat162*)lo)[2 * i + 1] = __halves2bfloat162(l2, l3);
}

// Row softmax (2048 cols) fused with hi/lo bf16 conversion.
__global__ void __launch_bounds__(256)
softmax_kernel(const float* __restrict__ S, __nv_bfloat16* __restrict__ Ahi,
               __nv_bfloat16* __restrict__ Alo)
{
    __shared__ float red[8];
    const long long row = blockIdx.x;
    const float* p = S + row * 2048ll;
    const int tid = threadIdx.x, lane = tid & 31, warp = tid >> 5;

    float v[8];
#pragma unroll
    for (int i = 0; i < 8; i++) v[i] = p[tid + 256 * i];

    float m = v[0];
#pragma unroll
    for (int i = 1; i < 8; i++) m = fmaxf(m, v[i]);
#pragma unroll
    for (int o = 16; o > 0; o >>= 1) m = fmaxf(m, __shfl_xor_sync(0xffffffffu, m, o));
    if (lane == 0) red[warp] = m;
    __syncthreads();
    float bm = red[0];
#pragma unroll
    for (int w = 1; w < 8; w++) bm = fmaxf(bm, red[w]);

    float s = 0.0f;
#pragma unroll
    for (int i = 0; i < 8; i++) { v[i] = __expf(v[i] - bm); s += v[i]; }
#pragma unroll
    for (int o = 16; o > 0; o >>= 1) s += __shfl_xor_sync(0xffffffffu, s, o);
    __syncthreads();
    if (lane == 0) red[warp] = s;
    __syncthreads();
    float bs = red[0];
#pragma unroll
    for (int w = 1; w < 8; w++) bs += red[w];

    const float inv = 1.0f / bs;
#pragma unroll
    for (int i = 0; i < 8; i++) {
        const float o = v[i] * inv;
        const long long idx = row * 2048ll + tid + 256 * i;
        const __nv_bfloat16 h = __float2bfloat16(o);
        Ahi[idx] = h;
        Alo[idx] = __float2bfloat16(o - __bfloat162float(h));
    }
}

// ---------------- launch ----------------
extern "C" void kernel_launch(void* const* d_in, const int* in_sizes, int n_in,
                              void* d_out, int out_size)
{
    const float* x  = (const float*)d_in[0];
    const float* Wq = (const float*)d_in[1];
    const float* bq = (const float*)d_in[2];
    const float* Wk = (const float*)d_in[3];
    const float* bk = (const float*)d_in[4];
    const float* Wv = (const float*)d_in[5];
    const float* bv = (const float*)d_in[6];
    const float* Wo = (const float*)d_in[7];
    const float* bo = (const float*)d_in[8];
    float* out = (float*)d_out;

    __nv_bfloat16 *xhi, *xlo, *wthi, *wtlo, *qhi, *qlo, *khi, *klo;
    __nv_bfloat16 *vthi, *vtlo, *athi, *atlo, *aohi, *aolo;
    float* s;
    cudaGetSymbolAddress((void**)&xhi, g_xhi);   cudaGetSymbolAddress((void**)&xlo, g_xlo);
    cudaGetSymbolAddress((void**)&wthi, g_wthi); cudaGetSymbolAddress((void**)&wtlo, g_wtlo);
    cudaGetSymbolAddress((void**)&qhi, g_qhi);   cudaGetSymbolAddress((void**)&qlo, g_qlo);
    cudaGetSymbolAddress((void**)&khi, g_khi);   cudaGetSymbolAddress((void**)&klo, g_klo);
    cudaGetSymbolAddress((void**)&vthi, g_vthi); cudaGetSymbolAddress((void**)&vtlo, g_vtlo);
    cudaGetSymbolAddress((void**)&s, g_s);
    cudaGetSymbolAddress((void**)&athi, g_athi); cudaGetSymbolAddress((void**)&atlo, g_atlo);
    cudaGetSymbolAddress((void**)&aohi, g_aohi); cudaGetSymbolAddress((void**)&aolo, g_aolo);

    cudaFuncSetAttribute(mma_gemm, cudaFuncAttributeMaxDynamicSharedMemorySize, SM_BYTES);

    const float scale = 1.0f / sqrtf((float)EE);

    // P0: prep
    wprep<<<dim3(24, 24, 4), dim3(32, 8)>>>(Wq, Wk, Wv, Wo, wthi, wtlo);
    const int n4 = MM * EE / 4;
    xsplit<<<(n4 + 255) / 256, 256>>>(x, xhi, xlo, n4);

    // S1: q, k projections  (M=16384, N=768, K=768)
    mma_gemm<<<dim3(6, 128, 1), 256, SM_BYTES>>>(
        xhi, xlo, EE, 0, wthi + 0 * WW, wtlo + 0 * WW, EE, 0,
        nullptr, qhi, qlo, EE, 0, EE, bq, 0, 1.0f);
    mma_gemm<<<dim3(6, 128, 1), 256, SM_BYTES>>>(
        xhi, xlo, EE, 0, wthi + 1 * WW, wtlo + 1 * WW, EE, 0,
        nullptr, khi, klo, EE, 0, EE, bk, 0, 1.0f);
    // S1v: vT[f][t] per batch  (A=WvT [768,768], B=x rows of batch, bias per-row)
    mma_gemm<<<dim3(16, 6, 8), 256, SM_BYTES>>>(
        wthi + 2 * WW, wtlo + 2 * WW, EE, 0, xhi, xlo, EE, sNE,
        nullptr, vthi, vtlo, NN, (long long)EE * NN, EE, bv, 1, 1.0f);

    // S2: scores = q @ k^T * scale per batch  (M=N=2048, K=768)
    mma_gemm<<<dim3(16, 16, 8), 256, SM_BYTES>>>(
        qhi, qlo, EE, sNE, khi, klo, EE, sNE,
        s, nullptr, nullptr, NN, sNN, EE, nullptr, 0, scale);

    // S3: softmax + bf16 split
    softmax_kernel<<<MM, 256>>>(s, athi, atlo);

    // S4: ao = attn @ v per batch  (M=2048, N=768, K=2048), B = vT K-major
    mma_gemm<<<dim3(6, 16, 8), 256, SM_BYTES>>>(
        athi, atlo, NN, sNN, vthi, vtlo, NN, (long long)EE * NN,
        nullptr, aohi, aolo, EE, sNE, NN, nullptr, 0, 1.0f);

    // S5: out = ao @ Wo^T + bo
    mma_gemm<<<dim3(6, 128, 1), 256, SM_BYTES>>>(
        aohi, aolo, EE, 0, wthi + 3 * WW, wtlo + 3 * WW, EE, 0,
        out, nullptr, nullptr, EE, 0, EE, bo, 0, 1.0f);
}

// round 8
// speedup vs baseline: 3.1708x; 1.1411x over previous
#include <cuda_runtime.h>
#include <cuda_bf16.h>
#include <cstdint>
#include <math.h>

// ViT self-attention, B=8, N=2048, E=768, single head, fp32 in/out.
// All GEMMs on warp-level tensor cores (mma.sync m16n8k16 bf16, fp32 accum)
// with split-bf16 (hi+lo) emulated fp32: D += Ahi*Bhi + Ahi*Blo + Alo*Bhi.
// R8: 3-stage cp.async pipeline, ONE __syncthreads per chunk, XOR-swizzled
// smem (no padding) -> 32KB/stage, 3 stages, 2 CTAs/SM.

// ---------------- dims / scratch ----------------
static constexpr int BB = 8, NN = 2048, EE = 768;
static constexpr int MM = BB * NN;                  // 16384
static constexpr long long sNE = (long long)NN * EE;
static constexpr long long sNN = (long long)NN * NN;
static constexpr int WW = EE * EE;

__device__ __nv_bfloat16 g_xhi[MM * EE],  g_xlo[MM * EE];
__device__ __nv_bfloat16 g_wthi[4 * WW],  g_wtlo[4 * WW];
__device__ __nv_bfloat16 g_qhi[MM * EE],  g_qlo[MM * EE];
__device__ __nv_bfloat16 g_khi[MM * EE],  g_klo[MM * EE];
__device__ __nv_bfloat16 g_vthi[BB * EE * NN], g_vtlo[BB * EE * NN];
__device__ float         g_s[BB * sNN];
__device__ __nv_bfloat16 g_athi[BB * sNN], g_atlo[BB * sNN];
__device__ __nv_bfloat16 g_aohi[MM * EE], g_aolo[MM * EE];

// ---------------- PTX helpers ----------------
__device__ __forceinline__ uint32_t smem_u32(const void* p) {
    uint32_t a;
    asm("{ .reg .u64 t; cvta.to.shared.u64 t, %1; cvt.u32.u64 %0, t; }" : "=r"(a) : "l"(p));
    return a;
}
__device__ __forceinline__ void ldsm_x4(uint32_t* r, uint32_t addr) {
    asm volatile("ldmatrix.sync.aligned.m8n8.x4.shared.b16 {%0,%1,%2,%3}, [%4];"
                 : "=r"(r[0]), "=r"(r[1]), "=r"(r[2]), "=r"(r[3]) : "r"(addr));
}
__device__ __forceinline__ void mma16816(float* d, const uint32_t* a, const uint32_t* b) {
    asm volatile(
        "mma.sync.aligned.m16n8k16.row.col.f32.bf16.bf16.f32 "
        "{%0,%1,%2,%3}, {%4,%5,%6,%7}, {%8,%9}, {%0,%1,%2,%3};"
        : "+f"(d[0]), "+f"(d[1]), "+f"(d[2]), "+f"(d[3])
        : "r"(a[0]), "r"(a[1]), "r"(a[2]), "r"(a[3]), "r"(b[0]), "r"(b[1]));
}
__device__ __forceinline__ void cp_async16(uint32_t saddr, const void* g) {
    asm volatile("cp.async.cg.shared.global [%0], [%1], 16;" :: "r"(saddr), "l"(g));
}
#define CP_COMMIT() asm volatile("cp.async.commit_group;" ::: "memory")
#define CP_WAIT(n)  asm volatile("cp.async.wait_group %0;" :: "n"(n) : "memory")

// ---------------- smem layout ----------------
// Per stage: 4 tiles of 128 rows x 32 bf16 (64B rows, no padding).
// Swizzle: 16B chunk c at row r stored at chunk (c ^ ((r>>1)&3)).
// Conflict-free for STS.128 phases and all ldmatrix 8-lane phases.
static constexpr int SA_HI = 0;
static constexpr int SA_LO = 8192;
static constexpr int SB_HI = 16384;
static constexpr int SB_LO = 24576;
static constexpr int STAGE = 32768;
static constexpr int NSTAGE = 3;
static constexpr int SM_BYTES = NSTAGE * STAGE;   // 98304 (dynamic)

// ---------------- tensor-core GEMM ----------------
// C[m,n] = alpha * sum_k A[m,k]*B[n,k] (+ bias), A/B split hi/lo bf16 K-major.
// CTA tile 128x128, BK=32, 3-stage cp.async pipeline, one barrier/chunk.
// 8 warps: 2(M)x4(N), warp tile 64x32. Grid: (N/128, M/128, batch).
__global__ void __launch_bounds__(256, 2)
mma_gemm(const __nv_bfloat16* __restrict__ Ahi, const __nv_bfloat16* __restrict__ Alo,
         long long lda, long long strideA,
         const __nv_bfloat16* __restrict__ Bhi, const __nv_bfloat16* __restrict__ Blo,
         long long ldb, long long strideB,
         float* __restrict__ Cf32,
         __nv_bfloat16* __restrict__ Chi, __nv_bfloat16* __restrict__ Clo,
         long long ldc, long long strideC,
         int K, const float* __restrict__ bias, int bias_row, float alpha)
{
    extern __shared__ __align__(16) char sm[];
    const uint32_t smb = smem_u32(sm);
    const int tid = threadIdx.x, wid = tid >> 5, lane = tid & 31;
    const int m0 = blockIdx.y * 128, n0 = blockIdx.x * 128;
    const long long z = blockIdx.z;
    const int m_w = (wid >> 2) * 64;   // warp M offset (0,64)
    const int n_w = (wid & 3) * 32;    // warp N offset (0,32,64,96)

    Ahi += z * strideA; Alo += z * strideA;
    Bhi += z * strideB; Blo += z * strideB;

    // ldmatrix addressing: row base (row*64) + xor nibble; chunk = kk*2 + c.
    uint32_t aRowH[4], aRowL[4], aXor[4];
    uint32_t bRowH[2], bRowL[2], bXor[2];
    const uint32_t cA16 = ((uint32_t)(lane >> 4)) << 4;        // A chunk sel *16
    const uint32_t cB16 = ((uint32_t)((lane >> 3) & 1)) << 4;  // B chunk sel *16
    {
        const uint32_t ar = m_w + (lane & 15);
#pragma unroll
        for (int i = 0; i < 4; i++) {
            const uint32_t r = ar + i * 16;
            aRowH[i] = SA_HI + r * 64;
            aRowL[i] = SA_LO + r * 64;
            aXor[i] = ((r >> 1) & 3) << 4;
        }
        const uint32_t br = n_w + (lane & 7) + ((lane >> 4) & 1) * 8;
#pragma unroll
        for (int p = 0; p < 2; p++) {
            const uint32_t r = br + p * 16;
            bRowH[p] = SB_HI + r * 64;
            bRowL[p] = SB_LO + r * 64;
            bXor[p] = ((r >> 1) & 3) << 4;
        }
    }

    float acc[4][4][4];
#pragma unroll
    for (int i = 0; i < 4; i++)
#pragma unroll
        for (int j = 0; j < 4; j++)
#pragma unroll
            for (int c = 0; c < 4; c++) acc[i][j][c] = 0.0f;

    const int nch = K >> 5;

    // issue async loads for chunk ck into stage st (2 slots/thread/tile)
    auto issue = [&](int ck, int st) {
        const int kt = ck << 5;
        const uint32_t sb = smb + st * STAGE;
#pragma unroll
        for (int it = 0; it < 2; it++) {
            const int slot = tid + it * 256;      // 0..511
            const int r = slot >> 2;              // row 0..127
            const int ch = slot & 3;              // 16B chunk 0..3
            const uint32_t so = (uint32_t)(r * 64 + ((ch ^ ((r >> 1) & 3)) << 4));
            const long long ga = (long long)(m0 + r) * lda + kt + ch * 8;
            const long long gb = (long long)(n0 + r) * ldb + kt + ch * 8;
            cp_async16(sb + SA_HI + so, Ahi + ga);
            cp_async16(sb + SA_LO + so, Alo + ga);
            cp_async16(sb + SB_HI + so, Bhi + gb);
            cp_async16(sb + SB_LO + so, Blo + gb);
        }
        CP_COMMIT();
    };

    issue(0, 0);
    if (nch > 1) issue(1, 1);

    int st = 0;
    for (int ck = 0; ck < nch; ck++) {
        if (ck + 2 < nch) { CP_WAIT(1); } else { CP_WAIT(0); }
        __syncthreads();                 // stage ck ready; compute ck-1 done everywhere
        if (ck + 2 < nch) {
            int st2 = st + 2; if (st2 >= NSTAGE) st2 -= NSTAGE;
            issue(ck + 2, st2);
        }

        const uint32_t sb = smb + st * STAGE;
#pragma unroll
        for (int kk = 0; kk < 2; kk++) {
            const uint32_t kk32 = kk * 32;
            uint32_t afH[4][4], afL[4][4], bf[2][4];
            // 12 ldsm.x4 per k-half (A-hi, A-lo, B-hi, B-lo each once)
#pragma unroll
            for (int i = 0; i < 4; i++)
                ldsm_x4(afH[i], sb + aRowH[i] + ((kk32 + cA16) ^ aXor[i]));
#pragma unroll
            for (int p = 0; p < 2; p++)
                ldsm_x4(bf[p], sb + bRowH[p] + ((kk32 + cB16) ^ bXor[p]));
            // pass 1: Ahi * Bhi
#pragma unroll
            for (int i = 0; i < 4; i++)
#pragma unroll
                for (int j = 0; j < 4; j++)
                    mma16816(acc[i][j], afH[i], &bf[j >> 1][(j & 1) * 2]);
            // pass 2: Alo * Bhi (B-hi resident)
#pragma unroll
            for (int i = 0; i < 4; i++)
                ldsm_x4(afL[i], sb + aRowL[i] + ((kk32 + cA16) ^ aXor[i]));
#pragma unroll
            for (int i = 0; i < 4; i++)
#pragma unroll
                for (int j = 0; j < 4; j++)
                    mma16816(acc[i][j], afL[i], &bf[j >> 1][(j & 1) * 2]);
            // pass 3: Ahi * Blo (A-hi resident)
#pragma unroll
            for (int p = 0; p < 2; p++)
                ldsm_x4(bf[p], sb + bRowL[p] + ((kk32 + cB16) ^ bXor[p]));
#pragma unroll
            for (int i = 0; i < 4; i++)
#pragma unroll
                for (int j = 0; j < 4; j++)
                    mma16816(acc[i][j], afH[i], &bf[j >> 1][(j & 1) * 2]);
        }
        st++; if (st >= NSTAGE) st = 0;
    }

    // ---- epilogue ----
#pragma unroll
    for (int i = 0; i < 4; i++) {
#pragma unroll
        for (int h = 0; h < 2; h++) {
            const int row = m0 + m_w + i * 16 + (lane >> 2) + h * 8;
            const float brow = (bias && bias_row) ? bias[row] : 0.0f;
            const long long rbase = z * strideC + (long long)row * ldc;
#pragma unroll
            for (int j = 0; j < 4; j++) {
                const int col = n0 + n_w + j * 8 + 2 * (lane & 3);
                float v0 = acc[i][j][h * 2 + 0] * alpha;
                float v1 = acc[i][j][h * 2 + 1] * alpha;
                if (bias) {
                    if (bias_row) { v0 += brow; v1 += brow; }
                    else          { v0 += bias[col]; v1 += bias[col + 1]; }
                }
                if (Cf32) {
                    float2 w; w.x = v0; w.y = v1;
                    *(float2*)(Cf32 + rbase + col) = w;
                }
                if (Chi) {
                    const __nv_bfloat16 h0 = __float2bfloat16(v0);
                    const __nv_bfloat16 h1 = __float2bfloat16(v1);
                    *(__nv_bfloat162*)(Chi + rbase + col) = __halves2bfloat162(h0, h1);
                    const __nv_bfloat16 l0 = __float2bfloat16(v0 - __bfloat162float(h0));
                    const __nv_bfloat16 l1 = __float2bfloat16(v1 - __bfloat162float(h1));
                    *(__nv_bfloat162*)(Clo + rbase + col) = __halves2bfloat162(l0, l1);
                }
            }
        }
    }
}

// ---------------- prep kernels ----------------
__global__ void __launch_bounds__(256)
wprep(const float* __restrict__ W0, const float* __restrict__ W1,
      const float* __restrict__ W2, const float* __restrict__ W3,
      __nv_bfloat16* __restrict__ hi, __nv_bfloat16* __restrict__ lo)
{
    __shared__ float t[32][33];
    const int zi = blockIdx.z;
    const float* W = (zi == 0) ? W0 : (zi == 1) ? W1 : (zi == 2) ? W2 : W3;
    __nv_bfloat16* H = hi + (long long)zi * WW;
    __nv_bfloat16* L = lo + (long long)zi * WW;
    const int bx = blockIdx.x * 32, by = blockIdx.y * 32;
    const int tx = threadIdx.x, ty = threadIdx.y;
#pragma unroll
    for (int i = 0; i < 32; i += 8)
        t[ty + i][tx] = W[(long long)(by + ty + i) * EE + bx + tx];
    __syncthreads();
#pragma unroll
    for (int i = 0; i < 32; i += 8) {
        const float v = t[tx][ty + i];
        const __nv_bfloat16 h = __float2bfloat16(v);
        const long long o = (long long)(bx + ty + i) * EE + by + tx;
        H[o] = h;
        L[o] = __float2bfloat16(v - __bfloat162float(h));
    }
}

__global__ void __launch_bounds__(256)
xsplit(const float* __restrict__ x, __nv_bfloat16* __restrict__ hi,
       __nv_bfloat16* __restrict__ lo, int n4)
{
    const int i = blockIdx.x * blockDim.x + threadIdx.x;
    if (i >= n4) return;
    const float4 v = ((const float4*)x)[i];
    __nv_bfloat16 h0 = __float2bfloat16(v.x), h1 = __float2bfloat16(v.y);
    __nv_bfloat16 h2 = __float2bfloat16(v.z), h3 = __float2bfloat16(v.w);
    ((__nv_bfloat162*)hi)[2 * i]     = __halves2bfloat162(h0, h1);
    ((__nv_bfloat162*)hi)[2 * i + 1] = __halves2bfloat162(h2, h3);
    __nv_bfloat16 l0 = __float2bfloat16(v.x - __bfloat162float(h0));
    __nv_bfloat16 l1 = __float2bfloat16(v.y - __bfloat162float(h1));
    __nv_bfloat16 l2 = __float2bfloat16(v.z - __bfloat162float(h2));
    __nv_bfloat16 l3 = __float2bfloat16(v.w - __bfloat162float(h3));
    ((__nv_bfloat162*)lo)[2 * i]     = __halves2bfloat162(l0, l1);
    ((__nv_bfloat162*)lo)[2 * i + 1] = __halves2bfloat162(l2, l3);
}

// Row softmax (2048 cols) fused with hi/lo bf16 conversion.
__global__ void __launch_bounds__(256)
softmax_kernel(const float* __restrict__ S, __nv_bfloat16* __restrict__ Ahi,
               __nv_bfloat16* __restrict__ Alo)
{
    __shared__ float red[8];
    const long long row = blockIdx.x;
    const float* p = S + row * 2048ll;
    const int tid = threadIdx.x, lane = tid & 31, warp = tid >> 5;

    float v[8];
#pragma unroll
    for (int i = 0; i < 8; i++) v[i] = p[tid + 256 * i];

    float m = v[0];
#pragma unroll
    for (int i = 1; i < 8; i++) m = fmaxf(m, v[i]);
#pragma unroll
    for (int o = 16; o > 0; o >>= 1) m = fmaxf(m, __shfl_xor_sync(0xffffffffu, m, o));
    if (lane == 0) red[warp] = m;
    __syncthreads();
    float bm = red[0];
#pragma unroll
    for (int w = 1; w < 8; w++) bm = fmaxf(bm, red[w]);

    float s = 0.0f;
#pragma unroll
    for (int i = 0; i < 8; i++) { v[i] = __expf(v[i] - bm); s += v[i]; }
#pragma unroll
    for (int o = 16; o > 0; o >>= 1) s += __shfl_xor_sync(0xffffffffu, s, o);
    __syncthreads();
    if (lane == 0) red[warp] = s;
    __syncthreads();
    float bs = red[0];
#pragma unroll
    for (int w = 1; w < 8; w++) bs += red[w];

    const float inv = 1.0f / bs;
#pragma unroll
    for (int i = 0; i < 8; i++) {
        const float o = v[i] * inv;
        const long long idx = row * 2048ll + tid + 256 * i;
        const __nv_bfloat16 h = __float2bfloat16(o);
        Ahi[idx] = h;
        Alo[idx] = __float2bfloat16(o - __bfloat162float(h));
    }
}

// ---------------- launch ----------------
extern "C" void kernel_launch(void* const* d_in, const int* in_sizes, int n_in,
                              void* d_out, int out_size)
{
    const float* x  = (const float*)d_in[0];
    const float* Wq = (const float*)d_in[1];
    const float* bq = (const float*)d_in[2];
    const float* Wk = (const float*)d_in[3];
    const float* bk = (const float*)d_in[4];
    const float* Wv = (const float*)d_in[5];
    const float* bv = (const float*)d_in[6];
    const float* Wo = (const float*)d_in[7];
    const float* bo = (const float*)d_in[8];
    float* out = (float*)d_out;

    __nv_bfloat16 *xhi, *xlo, *wthi, *wtlo, *qhi, *qlo, *khi, *klo;
    __nv_bfloat16 *vthi, *vtlo, *athi, *atlo, *aohi, *aolo;
    float* s;
    cudaGetSymbolAddress((void**)&xhi, g_xhi);   cudaGetSymbolAddress((void**)&xlo, g_xlo);
    cudaGetSymbolAddress((void**)&wthi, g_wthi); cudaGetSymbolAddress((void**)&wtlo, g_wtlo);
    cudaGetSymbolAddress((void**)&qhi, g_qhi);   cudaGetSymbolAddress((void**)&qlo, g_qlo);
    cudaGetSymbolAddress((void**)&khi, g_khi);   cudaGetSymbolAddress((void**)&klo, g_klo);
    cudaGetSymbolAddress((void**)&vthi, g_vthi); cudaGetSymbolAddress((void**)&vtlo, g_vtlo);
    cudaGetSymbolAddress((void**)&s, g_s);
    cudaGetSymbolAddress((void**)&athi, g_athi); cudaGetSymbolAddress((void**)&atlo, g_atlo);
    cudaGetSymbolAddress((void**)&aohi, g_aohi); cudaGetSymbolAddress((void**)&aolo, g_aolo);

    cudaFuncSetAttribute(mma_gemm, cudaFuncAttributeMaxDynamicSharedMemorySize, SM_BYTES);

    const float scale = 1.0f / sqrtf((float)EE);

    // P0: prep
    wprep<<<dim3(24, 24, 4), dim3(32, 8)>>>(Wq, Wk, Wv, Wo, wthi, wtlo);
    const int n4 = MM * EE / 4;
    xsplit<<<(n4 + 255) / 256, 256>>>(x, xhi, xlo, n4);

    // S1: q, k projections  (M=16384, N=768, K=768)
    mma_gemm<<<dim3(6, 128, 1), 256, SM_BYTES>>>(
        xhi, xlo, EE, 0, wthi + 0 * WW, wtlo + 0 * WW, EE, 0,
        nullptr, qhi, qlo, EE, 0, EE, bq, 0, 1.0f);
    mma_gemm<<<dim3(6, 128, 1), 256, SM_BYTES>>>(
        xhi, xlo, EE, 0, wthi + 1 * WW, wtlo + 1 * WW, EE, 0,
        nullptr, khi, klo, EE, 0, EE, bk, 0, 1.0f);
    // S1v: vT[f][t] per batch  (A=WvT [768,768], B=x rows of batch, bias per-row)
    mma_gemm<<<dim3(16, 6, 8), 256, SM_BYTES>>>(
        wthi + 2 * WW, wtlo + 2 * WW, EE, 0, xhi, xlo, EE, sNE,
        nullptr, vthi, vtlo, NN, (long long)EE * NN, EE, bv, 1, 1.0f);

    // S2: scores = q @ k^T * scale per batch  (M=N=2048, K=768)
    mma_gemm<<<dim3(16, 16, 8), 256, SM_BYTES>>>(
        qhi, qlo, EE, sNE, khi, klo, EE, sNE,
        s, nullptr, nullptr, NN, sNN, EE, nullptr, 0, scale);

    // S3: softmax + bf16 split
    softmax_kernel<<<MM, 256>>>(s, athi, atlo);

    // S4: ao = attn @ v per batch  (M=2048, N=768, K=2048), B = vT K-major
    mma_gemm<<<dim3(6, 16, 8), 256, SM_BYTES>>>(
        athi, atlo, NN, sNN, vthi, vtlo, NN, (long long)EE * NN,
        nullptr, aohi, aolo, EE, sNE, NN, nullptr, 0, 1.0f);

    // S5: out = ao @ Wo^T + bo
    mma_gemm<<<dim3(6, 128, 1), 256, SM_BYTES>>>(
        aohi, aolo, EE, 0, wthi + 3 * WW, wtlo + 3 * WW, EE, 0,
        out, nullptr, nullptr, EE, 0, EE, bo, 0, 1.0f);
}

// round 9
// speedup vs baseline: 3.2592x; 1.0279x over previous
#include <cuda_runtime.h>
#include <cuda_bf16.h>
#include <cstdint>
#include <math.h>

// ViT self-attention, B=8, N=2048, E=768, single head, fp32 in/out.
// All GEMMs on warp-level tensor cores (mma.sync m16n8k16 bf16, fp32 accum)
// with split-bf16 (hi+lo) emulated fp32: D += Ahi*Bhi + Ahi*Blo + Alo*Bhi.
// R9: merged Q+K projection (N=1536), pass-reordered mainloop for ldsm cover,
// int32 indexing. 3-stage cp.async pipeline, XOR-swizzled smem.

// ---------------- dims / scratch ----------------
static constexpr int BB = 8, NN = 2048, EE = 768;
static constexpr int MM = BB * NN;                  // 16384
static constexpr int E2 = 2 * EE;                   // 1536
static constexpr int WW = EE * EE;

__device__ __nv_bfloat16 g_xhi[MM * EE],  g_xlo[MM * EE];
__device__ __nv_bfloat16 g_wthi[4 * WW],  g_wtlo[4 * WW];
__device__ __nv_bfloat16 g_qkhi[MM * E2], g_qklo[MM * E2];       // q|k combined
__device__ __nv_bfloat16 g_vthi[BB * EE * NN], g_vtlo[BB * EE * NN];
__device__ float         g_s[(long long)BB * NN * NN];
__device__ __nv_bfloat16 g_athi[(long long)BB * NN * NN], g_atlo[(long long)BB * NN * NN];
__device__ __nv_bfloat16 g_aohi[MM * EE], g_aolo[MM * EE];

// ---------------- PTX helpers ----------------
__device__ __forceinline__ uint32_t smem_u32(const void* p) {
    uint32_t a;
    asm("{ .reg .u64 t; cvta.to.shared.u64 t, %1; cvt.u32.u64 %0, t; }" : "=r"(a) : "l"(p));
    return a;
}
__device__ __forceinline__ void ldsm_x4(uint32_t* r, uint32_t addr) {
    asm volatile("ldmatrix.sync.aligned.m8n8.x4.shared.b16 {%0,%1,%2,%3}, [%4];"
                 : "=r"(r[0]), "=r"(r[1]), "=r"(r[2]), "=r"(r[3]) : "r"(addr));
}
__device__ __forceinline__ void mma16816(float* d, const uint32_t* a, const uint32_t* b) {
    asm volatile(
        "mma.sync.aligned.m16n8k16.row.col.f32.bf16.bf16.f32 "
        "{%0,%1,%2,%3}, {%4,%5,%6,%7}, {%8,%9}, {%0,%1,%2,%3};"
        : "+f"(d[0]), "+f"(d[1]), "+f"(d[2]), "+f"(d[3])
        : "r"(a[0]), "r"(a[1]), "r"(a[2]), "r"(a[3]), "r"(b[0]), "r"(b[1]));
}
__device__ __forceinline__ void cp_async16(uint32_t saddr, const void* g) {
    asm volatile("cp.async.cg.shared.global [%0], [%1], 16;" :: "r"(saddr), "l"(g));
}
#define CP_COMMIT() asm volatile("cp.async.commit_group;" ::: "memory")
#define CP_WAIT(n)  asm volatile("cp.async.wait_group %0;" :: "n"(n) : "memory")

// ---------------- smem layout ----------------
// Per stage: 4 tiles of 128 rows x 32 bf16 (64B rows, XOR swizzle).
static constexpr int SA_HI = 0;
static constexpr int SA_LO = 8192;
static constexpr int SB_HI = 16384;
static constexpr int SB_LO = 24576;
static constexpr int STAGE = 32768;
static constexpr int NSTAGE = 3;
static constexpr int SM_BYTES = NSTAGE * STAGE;   // 98304 (dynamic)

// ---------------- tensor-core GEMM ----------------
// C[m,n] = alpha * sum_k A[m,k]*B[n,k] (+ bias), A/B split hi/lo bf16 K-major.
// CTA tile 128x128, BK=32, 3-stage cp.async pipeline, one barrier/chunk.
// 8 warps: 2(M)x4(N), warp tile 64x32. Grid: (N/128, M/128, batch).
// bias2: column-bias for cols >= 768 (merged q|k projection).
__global__ void __launch_bounds__(256, 2)
mma_gemm(const __nv_bfloat16* __restrict__ Ahi, const __nv_bfloat16* __restrict__ Alo,
         int lda, int strideA,
         const __nv_bfloat16* __restrict__ Bhi, const __nv_bfloat16* __restrict__ Blo,
         int ldb, int strideB,
         float* __restrict__ Cf32,
         __nv_bfloat16* __restrict__ Chi, __nv_bfloat16* __restrict__ Clo,
         int ldc, int strideC,
         int K, const float* __restrict__ bias, const float* __restrict__ bias2,
         int bias_row, float alpha)
{
    extern __shared__ __align__(16) char sm[];
    const uint32_t smb = smem_u32(sm);
    const int tid = threadIdx.x, wid = tid >> 5, lane = tid & 31;
    const int m0 = blockIdx.y * 128, n0 = blockIdx.x * 128;
    const int z = blockIdx.z;
    const int m_w = (wid >> 2) * 64;   // warp M offset (0,64)
    const int n_w = (wid & 3) * 32;    // warp N offset (0,32,64,96)

    Ahi += z * strideA; Alo += z * strideA;
    Bhi += z * strideB; Blo += z * strideB;

    // column-bias selector (merged q|k projection: cols >= 768 use bias2)
    const float* bcol = bias;
    if (bias && !bias_row && bias2 && n0 >= EE) bcol = bias2 - EE;

    // ldmatrix addressing: row base (row*64) + xor nibble; chunk = kk*2 + c.
    uint32_t aRowH[4], aRowL[4], aXor[4];
    uint32_t bRowH[2], bRowL[2], bXor[2];
    const uint32_t cA16 = ((uint32_t)(lane >> 4)) << 4;        // A chunk sel *16
    const uint32_t cB16 = ((uint32_t)((lane >> 3) & 1)) << 4;  // B chunk sel *16
    {
        const uint32_t ar = m_w + (lane & 15);
#pragma unroll
        for (int i = 0; i < 4; i++) {
            const uint32_t r = ar + i * 16;
            aRowH[i] = SA_HI + r * 64;
            aRowL[i] = SA_LO + r * 64;
            aXor[i] = ((r >> 1) & 3) << 4;
        }
        const uint32_t br = n_w + (lane & 7) + ((lane >> 4) & 1) * 8;
#pragma unroll
        for (int p = 0; p < 2; p++) {
            const uint32_t r = br + p * 16;
            bRowH[p] = SB_HI + r * 64;
            bRowL[p] = SB_LO + r * 64;
            bXor[p] = ((r >> 1) & 3) << 4;
        }
    }

    float acc[4][4][4];
#pragma unroll
    for (int i = 0; i < 4; i++)
#pragma unroll
        for (int j = 0; j < 4; j++)
#pragma unroll
            for (int c = 0; c < 4; c++) acc[i][j][c] = 0.0f;

    const int nch = K >> 5;

    // issue async loads for chunk ck into stage st (2 slots/thread/tile)
    auto issue = [&](int ck, int st) {
        const int kt = ck << 5;
        const uint32_t sb = smb + st * STAGE;
#pragma unroll
        for (int it = 0; it < 2; it++) {
            const int slot = tid + it * 256;      // 0..511
            const int r = slot >> 2;              // row 0..127
            const int ch = slot & 3;              // 16B chunk 0..3
            const uint32_t so = (uint32_t)(r * 64 + ((ch ^ ((r >> 1) & 3)) << 4));
            const int ga = (m0 + r) * lda + kt + ch * 8;
            const int gb = (n0 + r) * ldb + kt + ch * 8;
            cp_async16(sb + SA_HI + so, Ahi + ga);
            cp_async16(sb + SA_LO + so, Alo + ga);
            cp_async16(sb + SB_HI + so, Bhi + gb);
            cp_async16(sb + SB_LO + so, Blo + gb);
        }
        CP_COMMIT();
    };

    issue(0, 0);
    if (nch > 1) issue(1, 1);

    int st = 0;
    for (int ck = 0; ck < nch; ck++) {
        if (ck + 2 < nch) { CP_WAIT(1); } else { CP_WAIT(0); }
        __syncthreads();                 // stage ck ready; compute ck-1 done everywhere
        if (ck + 2 < nch) {
            int st2 = st + 2; if (st2 >= NSTAGE) st2 -= NSTAGE;
            issue(ck + 2, st2);
        }

        const uint32_t sb = smb + st * STAGE;
#pragma unroll
        for (int kk = 0; kk < 2; kk++) {
            const uint32_t kk32 = kk * 32;
            uint32_t afH[4][4], afL[4][4], bfH[2][4], bfL[2][4];
            // group 1: A-hi + B-hi
#pragma unroll
            for (int i = 0; i < 4; i++)
                ldsm_x4(afH[i], sb + aRowH[i] + ((kk32 + cA16) ^ aXor[i]));
#pragma unroll
            for (int p = 0; p < 2; p++)
                ldsm_x4(bfH[p], sb + bRowH[p] + ((kk32 + cB16) ^ bXor[p]));
            // pass 1: Ahi * Bhi
#pragma unroll
            for (int i = 0; i < 4; i++)
#pragma unroll
                for (int j = 0; j < 4; j++)
                    mma16816(acc[i][j], afH[i], &bfH[j >> 1][(j & 1) * 2]);
            // B-lo load (covered by pass 1 MMAs)
#pragma unroll
            for (int p = 0; p < 2; p++)
                ldsm_x4(bfL[p], sb + bRowL[p] + ((kk32 + cB16) ^ bXor[p]));
            // pass 2: Ahi * Blo (A-hi resident)
#pragma unroll
            for (int i = 0; i < 4; i++)
#pragma unroll
                for (int j = 0; j < 4; j++)
                    mma16816(acc[i][j], afH[i], &bfL[j >> 1][(j & 1) * 2]);
            // A-lo load (covered by pass 2 MMAs)
#pragma unroll
            for (int i = 0; i < 4; i++)
                ldsm_x4(afL[i], sb + aRowL[i] + ((kk32 + cA16) ^ aXor[i]));
            // pass 3: Alo * Bhi (B-hi resident)
#pragma unroll
            for (int i = 0; i < 4; i++)
#pragma unroll
                for (int j = 0; j < 4; j++)
                    mma16816(acc[i][j], afL[i], &bfH[j >> 1][(j & 1) * 2]);
        }
        st++; if (st >= NSTAGE) st = 0;
    }

    // ---- epilogue ----
#pragma unroll
    for (int i = 0; i < 4; i++) {
#pragma unroll
        for (int h = 0; h < 2; h++) {
            const int row = m0 + m_w + i * 16 + (lane >> 2) + h * 8;
            const float brow = (bias && bias_row) ? bias[row] : 0.0f;
            const int rbase = z * strideC + row * ldc;
#pragma unroll
            for (int j = 0; j < 4; j++) {
                const int col = n0 + n_w + j * 8 + 2 * (lane & 3);
                float v0 = acc[i][j][h * 2 + 0] * alpha;
                float v1 = acc[i][j][h * 2 + 1] * alpha;
                if (bias) {
                    if (bias_row) { v0 += brow; v1 += brow; }
                    else          { v0 += bcol[col]; v1 += bcol[col + 1]; }
                }
                if (Cf32) {
                    float2 w; w.x = v0; w.y = v1;
                    *(float2*)(Cf32 + rbase + col) = w;
                }
                if (Chi) {
                    const __nv_bfloat16 h0 = __float2bfloat16(v0);
                    const __nv_bfloat16 h1 = __float2bfloat16(v1);
                    *(__nv_bfloat162*)(Chi + rbase + col) = __halves2bfloat162(h0, h1);
                    const __nv_bfloat16 l0 = __float2bfloat16(v0 - __bfloat162float(h0));
                    const __nv_bfloat16 l1 = __float2bfloat16(v1 - __bfloat162float(h1));
                    *(__nv_bfloat162*)(Clo + rbase + col) = __halves2bfloat162(l0, l1);
                }
            }
        }
    }
}

// ---------------- prep kernels ----------------
__global__ void __launch_bounds__(256)
wprep(const float* __restrict__ W0, const float* __restrict__ W1,
      const float* __restrict__ W2, const float* __restrict__ W3,
      __nv_bfloat16* __restrict__ hi, __nv_bfloat16* __restrict__ lo)
{
    __shared__ float t[32][33];
    const int zi = blockIdx.z;
    const float* W = (zi == 0) ? W0 : (zi == 1) ? W1 : (zi == 2) ? W2 : W3;
    __nv_bfloat16* H = hi + zi * WW;
    __nv_bfloat16* L = lo + zi * WW;
    const int bx = blockIdx.x * 32, by = blockIdx.y * 32;
    const int tx = threadIdx.x, ty = threadIdx.y;
#pragma unroll
    for (int i = 0; i < 32; i += 8)
        t[ty + i][tx] = W[(by + ty + i) * EE + bx + tx];
    __syncthreads();
#pragma unroll
    for (int i = 0; i < 32; i += 8) {
        const float v = t[tx][ty + i];
        const __nv_bfloat16 h = __float2bfloat16(v);
        const int o = (bx + ty + i) * EE + by + tx;
        H[o] = h;
        L[o] = __float2bfloat16(v - __bfloat162float(h));
    }
}

__global__ void __launch_bounds__(256)
xsplit(const float* __restrict__ x, __nv_bfloat16* __restrict__ hi,
       __nv_bfloat16* __restrict__ lo, int n4)
{
    const int i = blockIdx.x * blockDim.x + threadIdx.x;
    if (i >= n4) return;
    const float4 v = ((const float4*)x)[i];
    __nv_bfloat16 h0 = __float2bfloat16(v.x), h1 = __float2bfloat16(v.y);
    __nv_bfloat16 h2 = __float2bfloat16(v.z), h3 = __float2bfloat16(v.w);
    ((__nv_bfloat162*)hi)[2 * i]     = __halves2bfloat162(h0, h1);
    ((__nv_bfloat162*)hi)[2 * i + 1] = __halves2bfloat162(h2, h3);
    __nv_bfloat16 l0 = __float2bfloat16(v.x - __bfloat162float(h0));
    __nv_bfloat16 l1 = __float2bfloat16(v.y - __bfloat162float(h1));
    __nv_bfloat16 l2 = __float2bfloat16(v.z - __bfloat162float(h2));
    __nv_bfloat16 l3 = __float2bfloat16(v.w - __bfloat162float(h3));
    ((__nv_bfloat162*)lo)[2 * i]     = __halves2bfloat162(l0, l1);
    ((__nv_bfloat162*)lo)[2 * i + 1] = __halves2bfloat162(l2, l3);
}

// Row softmax (2048 cols) fused with hi/lo bf16 conversion.
__global__ void __launch_bounds__(256)
softmax_kernel(const float* __restrict__ S, __nv_bfloat16* __restrict__ Ahi,
               __nv_bfloat16* __restrict__ Alo)
{
    __shared__ float red[8];
    const long long row = blockIdx.x;
    const float* p = S + row * 2048ll;
    const int tid = threadIdx.x, lane = tid & 31, warp = tid >> 5;

    float v[8];
#pragma unroll
    for (int i = 0; i < 8; i++) v[i] = p[tid + 256 * i];

    float m = v[0];
#pragma unroll
    for (int i = 1; i < 8; i++) m = fmaxf(m, v[i]);
#pragma unroll
    for (int o = 16; o > 0; o >>= 1) m = fmaxf(m, __shfl_xor_sync(0xffffffffu, m, o));
    if (lane == 0) red[warp] = m;
    __syncthreads();
    float bm = red[0];
#pragma unroll
    for (int w = 1; w < 8; w++) bm = fmaxf(bm, red[w]);

    float s = 0.0f;
#pragma unroll
    for (int i = 0; i < 8; i++) { v[i] = __expf(v[i] - bm); s += v[i]; }
#pragma unroll
    for (int o = 16; o > 0; o >>= 1) s += __shfl_xor_sync(0xffffffffu, s, o);
    __syncthreads();
    if (lane == 0) red[warp] = s;
    __syncthreads();
    float bs = red[0];
#pragma unroll
    for (int w = 1; w < 8; w++) bs += red[w];

    const float inv = 1.0f / bs;
#pragma unroll
    for (int i = 0; i < 8; i++) {
        const float o = v[i] * inv;
        const long long idx = row * 2048ll + tid + 256 * i;
        const __nv_bfloat16 h = __float2bfloat16(o);
        Ahi[idx] = h;
        Alo[idx] = __float2bfloat16(o - __bfloat162float(h));
    }
}

// ---------------- launch ----------------
extern "C" void kernel_launch(void* const* d_in, const int* in_sizes, int n_in,
                              void* d_out, int out_size)
{
    const float* x  = (const float*)d_in[0];
    const float* Wq = (const float*)d_in[1];
    const float* bq = (const float*)d_in[2];
    const float* Wk = (const float*)d_in[3];
    const float* bk = (const float*)d_in[4];
    const float* Wv = (const float*)d_in[5];
    const float* bv = (const float*)d_in[6];
    const float* Wo = (const float*)d_in[7];
    const float* bo = (const float*)d_in[8];
    float* out = (float*)d_out;

    __nv_bfloat16 *xhi, *xlo, *wthi, *wtlo, *qkhi, *qklo;
    __nv_bfloat16 *vthi, *vtlo, *athi, *atlo, *aohi, *aolo;
    float* s;
    cudaGetSymbolAddress((void**)&xhi, g_xhi);   cudaGetSymbolAddress((void**)&xlo, g_xlo);
    cudaGetSymbolAddress((void**)&wthi, g_wthi); cudaGetSymbolAddress((void**)&wtlo, g_wtlo);
    cudaGetSymbolAddress((void**)&qkhi, g_qkhi); cudaGetSymbolAddress((void**)&qklo, g_qklo);
    cudaGetSymbolAddress((void**)&vthi, g_vthi); cudaGetSymbolAddress((void**)&vtlo, g_vtlo);
    cudaGetSymbolAddress((void**)&s, g_s);
    cudaGetSymbolAddress((void**)&athi, g_athi); cudaGetSymbolAddress((void**)&atlo, g_atlo);
    cudaGetSymbolAddress((void**)&aohi, g_aohi); cudaGetSymbolAddress((void**)&aolo, g_aolo);

    cudaFuncSetAttribute(mma_gemm, cudaFuncAttributeMaxDynamicSharedMemorySize, SM_BYTES);

    const float scale = 1.0f / sqrtf((float)EE);
    const int sNE = NN * EE;        // 1,572,864
    const int sNN = NN * NN;        // 4,194,304
    const int sQK = NN * E2;        // 3,145,728

    // P0: prep
    wprep<<<dim3(24, 24, 4), dim3(32, 8)>>>(Wq, Wk, Wv, Wo, wthi, wtlo);
    const int n4 = MM * EE / 4;
    xsplit<<<(n4 + 255) / 256, 256>>>(x, xhi, xlo, n4);

    // S1qk: merged q|k projection  (M=16384, N=1536, K=768)
    // B rows 0..767 = Wq^T, 768..1535 = Wk^T (contiguous in wthi).
    mma_gemm<<<dim3(12, 128, 1), 256, SM_BYTES>>>(
        xhi, xlo, EE, 0, wthi, wtlo, EE, 0,
        nullptr, qkhi, qklo, E2, 0, EE, bq, bk, 0, 1.0f);

    // S1v: vT[f][t] per batch  (A=WvT [768,768], B=x rows of batch, bias per-row)
    mma_gemm<<<dim3(16, 6, 8), 256, SM_BYTES>>>(
        wthi + 2 * WW, wtlo + 2 * WW, EE, 0, xhi, xlo, EE, sNE,
        nullptr, vthi, vtlo, NN, EE * NN, EE, bv, nullptr, 1, 1.0f);

    // S2: scores = q @ k^T * scale per batch  (M=N=2048, K=768)
    mma_gemm<<<dim3(16, 16, 8), 256, SM_BYTES>>>(
        qkhi, qklo, E2, sQK, qkhi + EE, qklo + EE, E2, sQK,
        s, nullptr, nullptr, NN, sNN, EE, nullptr, nullptr, 0, scale);

    // S3: softmax + bf16 split
    softmax_kernel<<<MM, 256>>>(s, athi, atlo);

    // S4: ao = attn @ v per batch  (M=2048, N=768, K=2048), B = vT K-major
    mma_gemm<<<dim3(6, 16, 8), 256, SM_BYTES>>>(
        athi, atlo, NN, sNN, vthi, vtlo, NN, EE * NN,
        nullptr, aohi, aolo, EE, sNE, NN, nullptr, nullptr, 0, 1.0f);

    // S5: out = ao @ Wo^T + bo
    mma_gemm<<<dim3(6, 128, 1), 256, SM_BYTES>>>(
        aohi, aolo, EE, 0, wthi + 3 * WW, wtlo + 3 * WW, EE, 0,
        out, nullptr, nullptr, EE, 0, EE, bo, nullptr, 0, 1.0f);
}

// round 11
// speedup vs baseline: 3.2725x; 1.0041x over previous
#include <cuda_runtime.h>
#include <cuda_bf16.h>
#include <cstdint>
#include <math.h>

// ViT self-attention, B=8, N=2048, E=768, single head, fp32 in/out.
// All GEMMs on warp-level tensor cores (mma.sync m16n8k16 bf16, fp32 accum)
// with split-bf16 (hi+lo) emulated fp32: D += Ahi*Bhi + Ahi*Blo + Alo*Bhi.
// R11: truncation-based hi/lo split (PRMT + packed cvt.rn.bf16x2) everywhere,
// softmax on ex2.approx with log2e folded into the score scale.

// ---------------- dims / scratch ----------------
static constexpr int BB = 8, NN = 2048, EE = 768;
static constexpr int MM = BB * NN;                  // 16384
static constexpr int E2 = 2 * EE;                   // 1536
static constexpr int WW = EE * EE;

__device__ __nv_bfloat16 g_xhi[MM * EE],  g_xlo[MM * EE];
__device__ __nv_bfloat16 g_wthi[4 * WW],  g_wtlo[4 * WW];
__device__ __nv_bfloat16 g_qkhi[MM * E2], g_qklo[MM * E2];       // q|k combined
__device__ __nv_bfloat16 g_vthi[BB * EE * NN], g_vtlo[BB * EE * NN];
__device__ float         g_s[(long long)BB * NN * NN];
__device__ __nv_bfloat16 g_athi[(long long)BB * NN * NN], g_atlo[(long long)BB * NN * NN];
__device__ __nv_bfloat16 g_aohi[MM * EE], g_aolo[MM * EE];

// ---------------- PTX helpers ----------------
__device__ __forceinline__ uint32_t smem_u32(const void* p) {
    uint32_t a;
    asm("{ .reg .u64 t; cvta.to.shared.u64 t, %1; cvt.u32.u64 %0, t; }" : "=r"(a) : "l"(p));
    return a;
}
__device__ __forceinline__ void ldsm_x4(uint32_t* r, uint32_t addr) {
    asm volatile("ldmatrix.sync.aligned.m8n8.x4.shared.b16 {%0,%1,%2,%3}, [%4];"
                 : "=r"(r[0]), "=r"(r[1]), "=r"(r[2]), "=r"(r[3]) : "r"(addr));
}
__device__ __forceinline__ void mma16816(float* d, const uint32_t* a, const uint32_t* b) {
    asm volatile(
        "mma.sync.aligned.m16n8k16.row.col.f32.bf16.bf16.f32 "
        "{%0,%1,%2,%3}, {%4,%5,%6,%7}, {%8,%9}, {%0,%1,%2,%3};"
        : "+f"(d[0]), "+f"(d[1]), "+f"(d[2]), "+f"(d[3])
        : "r"(a[0]), "r"(a[1]), "r"(a[2]), "r"(a[3]), "r"(b[0]), "r"(b[1]));
}
__device__ __forceinline__ void cp_async16(uint32_t saddr, const void* g) {
    asm volatile("cp.async.cg.shared.global [%0], [%1], 16;" :: "r"(saddr), "l"(g));
}
#define CP_COMMIT() asm volatile("cp.async.commit_group;" ::: "memory")
#define CP_WAIT(n)  asm volatile("cp.async.wait_group %0;" :: "n"(n) : "memory")

__device__ __forceinline__ float ex2(float x) {
    float r;
    asm("ex2.approx.ftz.f32 %0, %1;" : "=f"(r) : "f"(x));
    return r;
}

// Truncation hi/lo split for a float pair -> packed bf16x2 words.
// hi = trunc-to-bf16 (PRMT of top bytes), lo = rn(x - hi) (packed cvt).
// Pair accuracy identical to round-nearest split: hi+lo ~ x to 2^-17.
__device__ __forceinline__ void split2(float v0, float v1, uint32_t& hi2, uint32_t& lo2) {
    const uint32_t x0 = __float_as_uint(v0), x1 = __float_as_uint(v1);
    hi2 = __byte_perm(x0, x1, 0x7632);
    const float l0 = v0 - __uint_as_float(x0 & 0xFFFF0000u);
    const float l1 = v1 - __uint_as_float(x1 & 0xFFFF0000u);
    asm("cvt.rn.bf16x2.f32 %0, %1, %2;" : "=r"(lo2) : "f"(l1), "f"(l0));
}

// ---------------- smem layout ----------------
static constexpr int SA_HI = 0;
static constexpr int SA_LO = 8192;
static constexpr int SB_HI = 16384;
static constexpr int SB_LO = 24576;
static constexpr int STAGE = 32768;
static constexpr int NSTAGE = 3;
static constexpr int SM_BYTES = NSTAGE * STAGE;   // 98304 (dynamic)

// ---------------- tensor-core GEMM ----------------
// C[m,n] = alpha * sum_k A[m,k]*B[n,k] (+ bias), A/B split hi/lo bf16 K-major.
// CTA tile 128x128, BK=32, 3-stage cp.async pipeline, one barrier/chunk.
// 8 warps: 2(M)x4(N), warp tile 64x32. Grid: (N/128, M/128, batch).
__global__ void __launch_bounds__(256, 2)
mma_gemm(const __nv_bfloat16* __restrict__ Ahi, const __nv_bfloat16* __restrict__ Alo,
         int lda, int strideA,
         const __nv_bfloat16* __restrict__ Bhi, const __nv_bfloat16* __restrict__ Blo,
         int ldb, int strideB,
         float* __restrict__ Cf32,
         __nv_bfloat16* __restrict__ Chi, __nv_bfloat16* __restrict__ Clo,
         int ldc, int strideC,
         int K, const float* __restrict__ bias, const float* __restrict__ bias2,
         int bias_row, float alpha)
{
    extern __shared__ __align__(16) char sm[];
    const uint32_t smb = smem_u32(sm);
    const int tid = threadIdx.x, wid = tid >> 5, lane = tid & 31;
    const int m0 = blockIdx.y * 128, n0 = blockIdx.x * 128;
    const int z = blockIdx.z;
    const int m_w = (wid >> 2) * 64;   // warp M offset (0,64)
    const int n_w = (wid & 3) * 32;    // warp N offset (0,32,64,96)

    Ahi += z * strideA; Alo += z * strideA;
    Bhi += z * strideB; Blo += z * strideB;

    // column-bias selector (merged q|k projection: cols >= 768 use bias2)
    const float* bcol = bias;
    if (bias && !bias_row && bias2 && n0 >= EE) bcol = bias2 - EE;

    uint32_t aRowH[4], aRowL[4], aXor[4];
    uint32_t bRowH[2], bRowL[2], bXor[2];
    const uint32_t cA16 = ((uint32_t)(lane >> 4)) << 4;
    const uint32_t cB16 = ((uint32_t)((lane >> 3) & 1)) << 4;
    {
        const uint32_t ar = m_w + (lane & 15);
#pragma unroll
        for (int i = 0; i < 4; i++) {
            const uint32_t r = ar + i * 16;
            aRowH[i] = SA_HI + r * 64;
            aRowL[i] = SA_LO + r * 64;
            aXor[i] = ((r >> 1) & 3) << 4;
        }
        const uint32_t br = n_w + (lane & 7) + ((lane >> 4) & 1) * 8;
#pragma unroll
        for (int p = 0; p < 2; p++) {
            const uint32_t r = br + p * 16;
            bRowH[p] = SB_HI + r * 64;
            bRowL[p] = SB_LO + r * 64;
            bXor[p] = ((r >> 1) & 3) << 4;
        }
    }

    float acc[4][4][4];
#pragma unroll
    for (int i = 0; i < 4; i++)
#pragma unroll
        for (int j = 0; j < 4; j++)
#pragma unroll
            for (int c = 0; c < 4; c++) acc[i][j][c] = 0.0f;

    const int nch = K >> 5;

    auto issue = [&](int ck, int st) {
        const int kt = ck << 5;
        const uint32_t sb = smb + st * STAGE;
#pragma unroll
        for (int it = 0; it < 2; it++) {
            const int slot = tid + it * 256;
            const int r = slot >> 2;
            const int ch = slot & 3;
            const uint32_t so = (uint32_t)(r * 64 + ((ch ^ ((r >> 1) & 3)) << 4));
            const int ga = (m0 + r) * lda + kt + ch * 8;
            const int gb = (n0 + r) * ldb + kt + ch * 8;
            cp_async16(sb + SA_HI + so, Ahi + ga);
            cp_async16(sb + SA_LO + so, Alo + ga);
            cp_async16(sb + SB_HI + so, Bhi + gb);
            cp_async16(sb + SB_LO + so, Blo + gb);
        }
        CP_COMMIT();
    };

    issue(0, 0);
    if (nch > 1) issue(1, 1);

    int st = 0;
    for (int ck = 0; ck < nch; ck++) {
        if (ck + 2 < nch) { CP_WAIT(1); } else { CP_WAIT(0); }
        __syncthreads();
        if (ck + 2 < nch) {
            int st2 = st + 2; if (st2 >= NSTAGE) st2 -= NSTAGE;
            issue(ck + 2, st2);
        }

        const uint32_t sb = smb + st * STAGE;
#pragma unroll
        for (int kk = 0; kk < 2; kk++) {
            const uint32_t kk32 = kk * 32;
            uint32_t afH[4][4], afL[4][4], bfH[2][4], bfL[2][4];
#pragma unroll
            for (int i = 0; i < 4; i++)
                ldsm_x4(afH[i], sb + aRowH[i] + ((kk32 + cA16) ^ aXor[i]));
#pragma unroll
            for (int p = 0; p < 2; p++)
                ldsm_x4(bfH[p], sb + bRowH[p] + ((kk32 + cB16) ^ bXor[p]));
            // pass 1: Ahi * Bhi
#pragma unroll
            for (int i = 0; i < 4; i++)
#pragma unroll
                for (int j = 0; j < 4; j++)
                    mma16816(acc[i][j], afH[i], &bfH[j >> 1][(j & 1) * 2]);
            // B-lo load (covered by pass 1)
#pragma unroll
            for (int p = 0; p < 2; p++)
                ldsm_x4(bfL[p], sb + bRowL[p] + ((kk32 + cB16) ^ bXor[p]));
            // pass 2: Ahi * Blo
#pragma unroll
            for (int i = 0; i < 4; i++)
#pragma unroll
                for (int j = 0; j < 4; j++)
                    mma16816(acc[i][j], afH[i], &bfL[j >> 1][(j & 1) * 2]);
            // A-lo load (covered by pass 2)
#pragma unroll
            for (int i = 0; i < 4; i++)
                ldsm_x4(afL[i], sb + aRowL[i] + ((kk32 + cA16) ^ aXor[i]));
            // pass 3: Alo * Bhi
#pragma unroll
            for (int i = 0; i < 4; i++)
#pragma unroll
                for (int j = 0; j < 4; j++)
                    mma16816(acc[i][j], afL[i], &bfH[j >> 1][(j & 1) * 2]);
        }
        st++; if (st >= NSTAGE) st = 0;
    }

    // ---- epilogue ----
#pragma unroll
    for (int i = 0; i < 4; i++) {
#pragma unroll
        for (int h = 0; h < 2; h++) {
            const int row = m0 + m_w + i * 16 + (lane >> 2) + h * 8;
            const float brow = (bias && bias_row) ? bias[row] : 0.0f;
            const int rbase = z * strideC + row * ldc;
#pragma unroll
            for (int j = 0; j < 4; j++) {
                const int col = n0 + n_w + j * 8 + 2 * (lane & 3);
                float v0 = acc[i][j][h * 2 + 0] * alpha;
                float v1 = acc[i][j][h * 2 + 1] * alpha;
                if (bias) {
                    if (bias_row) { v0 += brow; v1 += brow; }
                    else          { v0 += bcol[col]; v1 += bcol[col + 1]; }
                }
                if (Cf32) {
                    float2 w; w.x = v0; w.y = v1;
                    *(float2*)(Cf32 + rbase + col) = w;
                }
                if (Chi) {
                    uint32_t hi2, lo2;
                    split2(v0, v1, hi2, lo2);
                    *(uint32_t*)(Chi + rbase + col) = hi2;
                    *(uint32_t*)(Clo + rbase + col) = lo2;
                }
            }
        }
    }
}

// ---------------- prep kernels ----------------
// Transpose + split weights: hi = truncated bf16 (bit shift), lo = rn residual.
__global__ void __launch_bounds__(256)
wprep(const float* __restrict__ W0, const float* __restrict__ W1,
      const float* __restrict__ W2, const float* __restrict__ W3,
      __nv_bfloat16* __restrict__ hi, __nv_bfloat16* __restrict__ lo)
{
    __shared__ float t[32][33];
    const int zi = blockIdx.z;
    const float* W = (zi == 0) ? W0 : (zi == 1) ? W1 : (zi == 2) ? W2 : W3;
    uint16_t* H = (uint16_t*)hi + zi * WW;
    __nv_bfloat16* L = lo + zi * WW;
    const int bx = blockIdx.x * 32, by = blockIdx.y * 32;
    const int tx = threadIdx.x, ty = threadIdx.y;
#pragma unroll
    for (int i = 0; i < 32; i += 8)
        t[ty + i][tx] = W[(by + ty + i) * EE + bx + tx];
    __syncthreads();
#pragma unroll
    for (int i = 0; i < 32; i += 8) {
        const float v = t[tx][ty + i];
        const uint32_t vi = __float_as_uint(v);
        const int o = (bx + ty + i) * EE + by + tx;
        H[o] = (uint16_t)(vi >> 16);
        L[o] = __float2bfloat16(v - __uint_as_float(vi & 0xFFFF0000u));
    }
}

// Split x into hi/lo bf16 via truncation trick (vectorized).
__global__ void __launch_bounds__(256)
xsplit(const float* __restrict__ x, __nv_bfloat16* __restrict__ hi,
       __nv_bfloat16* __restrict__ lo, int n4)
{
    const int i = blockIdx.x * blockDim.x + threadIdx.x;
    if (i >= n4) return;
    const float4 v = ((const float4*)x)[i];
    uint32_t h01, l01, h23, l23;
    split2(v.x, v.y, h01, l01);
    split2(v.z, v.w, h23, l23);
    uint2 hw; hw.x = h01; hw.y = h23;
    uint2 lw; lw.x = l01; lw.y = l23;
    ((uint2*)hi)[i] = hw;
    ((uint2*)lo)[i] = lw;
}

// Row softmax (2048 cols). Input is pre-scaled by log2(e)/sqrt(E), so
// exp(score) == exp2(stored). Fused truncation hi/lo bf16 output.
__global__ void __launch_bounds__(256)
softmax_kernel(const float* __restrict__ S, __nv_bfloat16* __restrict__ Ahi,
               __nv_bfloat16* __restrict__ Alo)
{
    __shared__ float red[8];
    const long long row = blockIdx.x;
    const float2* p = (const float2*)(S + row * 2048ll);
    const int tid = threadIdx.x, lane = tid & 31, warp = tid >> 5;

    float2 v[4];
#pragma unroll
    for (int i = 0; i < 4; i++) v[i] = p[tid + 256 * i];

    float m = fmaxf(v[0].x, v[0].y);
#pragma unroll
    for (int i = 1; i < 4; i++) m = fmaxf(m, fmaxf(v[i].x, v[i].y));
#pragma unroll
    for (int o = 16; o > 0; o >>= 1) m = fmaxf(m, __shfl_xor_sync(0xffffffffu, m, o));
    if (lane == 0) red[warp] = m;
    __syncthreads();
    float bm = red[0];
#pragma unroll
    for (int w = 1; w < 8; w++) bm = fmaxf(bm, red[w]);

    float s = 0.0f;
#pragma unroll
    for (int i = 0; i < 4; i++) {
        v[i].x = ex2(v[i].x - bm);
        v[i].y = ex2(v[i].y - bm);
        s += v[i].x + v[i].y;
    }
#pragma unroll
    for (int o = 16; o > 0; o >>= 1) s += __shfl_xor_sync(0xffffffffu, s, o);
    __syncthreads();
    if (lane == 0) red[warp] = s;
    __syncthreads();
    float bs = red[0];
#pragma unroll
    for (int w = 1; w < 8; w++) bs += red[w];

    const float inv = 1.0f / bs;
    uint32_t* oh = (uint32_t*)Ahi + row * 1024ll;
    uint32_t* ol = (uint32_t*)Alo + row * 1024ll;
#pragma unroll
    for (int i = 0; i < 4; i++) {
        uint32_t hi2, lo2;
        split2(v[i].x * inv, v[i].y * inv, hi2, lo2);
        oh[tid + 256 * i] = hi2;
        ol[tid + 256 * i] = lo2;
    }
}

// ---------------- launch ----------------
extern "C" void kernel_launch(void* const* d_in, const int* in_sizes, int n_in,
                              void* d_out, int out_size)
{
    const float* x  = (const float*)d_in[0];
    const float* Wq = (const float*)d_in[1];
    const float* bq = (const float*)d_in[2];
    const float* Wk = (const float*)d_in[3];
    const float* bk = (const float*)d_in[4];
    const float* Wv = (const float*)d_in[5];
    const float* bv = (const float*)d_in[6];
    const float* Wo = (const float*)d_in[7];
    const float* bo = (const float*)d_in[8];
    float* out = (float*)d_out;

    __nv_bfloat16 *xhi, *xlo, *wthi, *wtlo, *qkhi, *qklo;
    __nv_bfloat16 *vthi, *vtlo, *athi, *atlo, *aohi, *aolo;
    float* s;
    cudaGetSymbolAddress((void**)&xhi, g_xhi);   cudaGetSymbolAddress((void**)&xlo, g_xlo);
    cudaGetSymbolAddress((void**)&wthi, g_wthi); cudaGetSymbolAddress((void**)&wtlo, g_wtlo);
    cudaGetSymbolAddress((void**)&qkhi, g_qkhi); cudaGetSymbolAddress((void**)&qklo, g_qklo);
    cudaGetSymbolAddress((void**)&vthi, g_vthi); cudaGetSymbolAddress((void**)&vtlo, g_vtlo);
    cudaGetSymbolAddress((void**)&s, g_s);
    cudaGetSymbolAddress((void**)&athi, g_athi); cudaGetSymbolAddress((void**)&atlo, g_atlo);
    cudaGetSymbolAddress((void**)&aohi, g_aohi); cudaGetSymbolAddress((void**)&aolo, g_aolo);

    cudaFuncSetAttribute(mma_gemm, cudaFuncAttributeMaxDynamicSharedMemorySize, SM_BYTES);

    // exp(score/sqrt(E)) == exp2(score * log2e/sqrt(E)) -> fold into S2 alpha.
    const float scale = 1.4426950408889634f / sqrtf((float)EE);
    const int sNE = NN * EE;
    const int sNN = NN * NN;
    const int sQK = NN * E2;

    // P0: prep
    wprep<<<dim3(24, 24, 4), dim3(32, 8)>>>(Wq, Wk, Wv, Wo, wthi, wtlo);
    const int n4 = MM * EE / 4;
    xsplit<<<(n4 + 255) / 256, 256>>>(x, xhi, xlo, n4);

    // S1qk: merged q|k projection  (M=16384, N=1536, K=768)
    mma_gemm<<<dim3(12, 128, 1), 256, SM_BYTES>>>(
        xhi, xlo, EE, 0, wthi, wtlo, EE, 0,
        nullptr, qkhi, qklo, E2, 0, EE, bq, bk, 0, 1.0f);

    // S1v: vT[f][t] per batch  (A=WvT [768,768], B=x rows of batch, bias per-row)
    mma_gemm<<<dim3(16, 6, 8), 256, SM_BYTES>>>(
        wthi + 2 * WW, wtlo + 2 * WW, EE, 0, xhi, xlo, EE, sNE,
        nullptr, vthi, vtlo, NN, EE * NN, EE, bv, nullptr, 1, 1.0f);

    // S2: scores = q @ k^T * (log2e/sqrt(E)) per batch  (M=N=2048, K=768)
    mma_gemm<<<dim3(16, 16, 8), 256, SM_BYTES>>>(
        qkhi, qklo, E2, sQK, qkhi + EE, qklo + EE, E2, sQK,
        s, nullptr, nullptr, NN, sNN, EE, nullptr, nullptr, 0, scale);

    // S3: softmax (exp2 domain) + truncation bf16 split
    softmax_kernel<<<MM, 256>>>(s, athi, atlo);

    // S4: ao = attn @ v per batch  (M=2048, N=768, K=2048), B = vT K-major
    mma_gemm<<<dim3(6, 16, 8), 256, SM_BYTES>>>(
        athi, atlo, NN, sNN, vthi, vtlo, NN, EE * NN,
        nullptr, aohi, aolo, EE, sNE, NN, nullptr, nullptr, 0, 1.0f);

    // S5: out = ao @ Wo^T + bo
    mma_gemm<<<dim3(6, 128, 1), 256, SM_BYTES>>>(
        aohi, aolo, EE, 0, wthi + 3 * WW, wtlo + 3 * WW, EE, 0,
        out, nullptr, nullptr, EE, 0, EE, bo, nullptr, 0, 1.0f);
}